// round 1
// baseline (speedup 1.0000x reference)
#include <cuda_runtime.h>
#include <math.h>

#define NB 8
#define NC 512
#define NS 1024
#define NHD 8
#define HD 64

// ---- scratch (static __device__, no allocs) ----
__device__ float g_h  [NB*NS*NC];        // groupnorm out, [B,S,C]
__device__ float g_q  [NB*NHD*NS*HD];    // [B,nh,S,hd]
__device__ float g_kk [NB*NHD*NS*HD];
__device__ float g_v  [NB*NHD*NS*HD];
__device__ float g_hf [NB*NS*NC];        // [B,S,C]
__device__ float g_hf2[NB*NS*NC];

// ============================================================
// GroupNorm: one block per (b, group). Group data is 64*1024
// contiguous floats in x's [B,C,H,W] layout.
// ============================================================
__global__ void groupnorm_kernel(const float* __restrict__ x,
                                 const float* __restrict__ gns,
                                 const float* __restrict__ gnb) {
    int b = blockIdx.x >> 3;
    int g = blockIdx.x & 7;
    const float* xp = x + (size_t)(b*NC + g*64) * NS;
    int tid = threadIdx.x;
    float s1 = 0.f, s2 = 0.f;
    for (int i = tid; i < 64*NS; i += 256) {
        float v = xp[i];
        s1 += v; s2 += v*v;
    }
    __shared__ float r1[256], r2[256];
    __shared__ float sm_mean, sm_inv;
    r1[tid] = s1; r2[tid] = s2;
    __syncthreads();
    for (int o = 128; o > 0; o >>= 1) {
        if (tid < o) { r1[tid] += r1[tid+o]; r2[tid] += r2[tid+o]; }
        __syncthreads();
    }
    if (tid == 0) {
        float mean = r1[0] * (1.f/65536.f);
        float var  = r2[0] * (1.f/65536.f) - mean*mean;
        sm_mean = mean;
        sm_inv  = rsqrtf(var + 1e-5f);
    }
    __syncthreads();
    float mean = sm_mean, inv = sm_inv;
    for (int i = tid; i < 64*NS; i += 256) {
        int cl = i >> 10, sp = i & 1023;     // channel-in-group, spatial
        int c = g*64 + cl;
        float v = (xp[i] - mean) * inv * gns[c] + gnb[c];
        g_h[(size_t)(b*NS + sp)*NC + c] = v; // write [B,S,C]
    }
}

// ============================================================
// Generic GEMM: C[M,N] = A[M,512] @ W[N,512]^T  (+ epilogue)
// BM=BN=64, BK=16, 256 threads, 4x4 micro-tile.
// MODE 0: qkv scatter   MODE 1: INL tanh step   MODE 2: proj + residual
// ============================================================
template<int MODE>
__global__ void gemm_kernel(const float* __restrict__ A,
                            const float* __restrict__ W,
                            const float* __restrict__ bias,
                            const float* __restrict__ addsrc,
                            float* __restrict__ out)
{
    __shared__ float As[16][64];
    __shared__ float Ws[16][64];
    int tid = threadIdx.x;
    int tx = tid & 15, ty = tid >> 4;
    int n0 = blockIdx.x << 6;
    int m0 = blockIdx.y << 6;
    int lr = tid >> 2;            // 0..63
    int lc = (tid & 3) << 2;      // 0,4,8,12
    const float* Ap = A + (size_t)(m0 + lr) * NC + lc;
    const float* Wp = W + (size_t)(n0 + lr) * NC + lc;
    float acc[4][4] = {};

    for (int kt = 0; kt < NC; kt += 16) {
        float4 av = *(const float4*)(Ap + kt);
        float4 wv = *(const float4*)(Wp + kt);
        As[lc+0][lr]=av.x; As[lc+1][lr]=av.y; As[lc+2][lr]=av.z; As[lc+3][lr]=av.w;
        Ws[lc+0][lr]=wv.x; Ws[lc+1][lr]=wv.y; Ws[lc+2][lr]=wv.z; Ws[lc+3][lr]=wv.w;
        __syncthreads();
#pragma unroll
        for (int k = 0; k < 16; k++) {
            float4 a = *(const float4*)&As[k][ty<<2];
            float4 w = *(const float4*)&Ws[k][tx<<2];
            acc[0][0]+=a.x*w.x; acc[0][1]+=a.x*w.y; acc[0][2]+=a.x*w.z; acc[0][3]+=a.x*w.w;
            acc[1][0]+=a.y*w.x; acc[1][1]+=a.y*w.y; acc[1][2]+=a.y*w.z; acc[1][3]+=a.y*w.w;
            acc[2][0]+=a.z*w.x; acc[2][1]+=a.z*w.y; acc[2][2]+=a.z*w.z; acc[2][3]+=a.z*w.w;
            acc[3][0]+=a.w*w.x; acc[3][1]+=a.w*w.y; acc[3][2]+=a.w*w.z; acc[3][3]+=a.w*w.w;
        }
        __syncthreads();
    }

#pragma unroll
    for (int i = 0; i < 4; i++) {
#pragma unroll
        for (int j = 0; j < 4; j++) {
            int m = m0 + (ty<<2) + i;
            int n = n0 + (tx<<2) + j;
            float val = acc[i][j] + bias[n];
            if (MODE == 0) {
                int b = m >> 10, sp = m & 1023;
                int which = n >> 9, oo = n & 511;
                int head = oo >> 6, d = oo & 63;
                float* dst = (which == 0) ? g_q : (which == 1) ? g_kk : g_v;
                dst[(size_t)((b*NHD + head)*NS + sp)*HD + d] = val;
            } else if (MODE == 1) {
                size_t idx = (size_t)m*NC + n;
                out[idx] = addsrc[idx] + 0.1f * tanhf(val);
            } else {
                int b = m >> 10, sp = m & 1023;
                size_t idx = (size_t)(b*NC + n)*NS + sp;
                out[idx] = addsrc[idx] + val;
            }
        }
    }
}

// ============================================================
// Flash attention: one CTA per (qtile=64 rows, head, batch).
// Smem: QsT[d][r] 16KB | KVs 16KB (K^T then V) | Ps[t][r] 16KB | stats
// ============================================================
__global__ void attn_kernel() {
    extern __shared__ float sm[];
    float* QsT   = sm;            // [64 d][64 r], pre-scaled by 1/8
    float* KVs   = sm + 4096;     // K phase: [64 d][64 t] ; V phase: [64 t][64 d]
    float* Ps    = sm + 8192;     // [64 t][64 r]  (S^T, then P^T)
    float* m_run = sm + 12288;    // [64]
    float* l_run = sm + 12352;    // [64]
    float* alph  = sm + 12416;    // [64]
    float* red   = sm + 12480;    // [256]

    int tid = threadIdx.x;
    int tx = tid & 15, ty = tid >> 4;
    int qt = blockIdx.x, h = blockIdx.y, b = blockIdx.z;
    const float* Qb = g_q  + (size_t)((b*NHD + h)*NS + (qt<<6)) * HD;
    const float* Kb = g_kk + (size_t)(b*NHD + h)*NS*HD;
    const float* Vb = g_v  + (size_t)(b*NHD + h)*NS*HD;

    // load Q transposed + scaled (bank-conflict-free STS: lane -> distinct r)
    {
        int r = tid & 63, dg = tid >> 6;
#pragma unroll
        for (int it = 0; it < 4; it++) {
            int d0 = it*16 + dg*4;
            float4 v = *(const float4*)(Qb + r*HD + d0);
            QsT[(d0+0)*64 + r] = v.x * 0.125f;
            QsT[(d0+1)*64 + r] = v.y * 0.125f;
            QsT[(d0+2)*64 + r] = v.z * 0.125f;
            QsT[(d0+3)*64 + r] = v.w * 0.125f;
        }
    }
    if (tid < 64) { m_run[tid] = -1e30f; l_run[tid] = 0.f; }
    float acc[4][4] = {};
    __syncthreads();

    int seg = tid >> 6;   // softmax: 4 threads per row
    int rr  = tid & 63;

    for (int kt = 0; kt < 16; kt++) {
        int t0 = kt << 6;
        // ---- load K transposed ----
        {
            int t = tid & 63, dg = tid >> 6;
#pragma unroll
            for (int it = 0; it < 4; it++) {
                int d0 = it*16 + dg*4;
                float4 v = *(const float4*)(Kb + (size_t)(t0 + t)*HD + d0);
                KVs[(d0+0)*64 + t] = v.x;
                KVs[(d0+1)*64 + t] = v.y;
                KVs[(d0+2)*64 + t] = v.z;
                KVs[(d0+3)*64 + t] = v.w;
            }
        }
        __syncthreads();
        // ---- phase A: S^T[t][r] = sum_d K^T[d][t] * Q^T[d][r] ----
        float sc[4][4] = {};
#pragma unroll 16
        for (int d = 0; d < 64; d++) {
            float4 kv = *(const float4*)&KVs[d*64 + (ty<<2)];
            float4 qv = *(const float4*)&QsT[d*64 + (tx<<2)];
            sc[0][0]+=kv.x*qv.x; sc[0][1]+=kv.x*qv.y; sc[0][2]+=kv.x*qv.z; sc[0][3]+=kv.x*qv.w;
            sc[1][0]+=kv.y*qv.x; sc[1][1]+=kv.y*qv.y; sc[1][2]+=kv.y*qv.z; sc[1][3]+=kv.y*qv.w;
            sc[2][0]+=kv.z*qv.x; sc[2][1]+=kv.z*qv.y; sc[2][2]+=kv.z*qv.z; sc[2][3]+=kv.z*qv.w;
            sc[3][0]+=kv.w*qv.x; sc[3][1]+=kv.w*qv.y; sc[3][2]+=kv.w*qv.z; sc[3][3]+=kv.w*qv.w;
        }
#pragma unroll
        for (int i = 0; i < 4; i++)
            *(float4*)&Ps[((ty<<2)+i)*64 + (tx<<2)] =
                make_float4(sc[i][0], sc[i][1], sc[i][2], sc[i][3]);
        __syncthreads();
        // ---- load V (linear) + softmax pass 1 (row max) ----
        {
            const float4* src  = (const float4*)(Vb + (size_t)t0*HD);
            float4* dst4 = (float4*)KVs;
#pragma unroll
            for (int it = 0; it < 4; it++)
                dst4[tid + it*256] = src[tid + it*256];
        }
        float pm = -1e30f;
#pragma unroll
        for (int tt = 0; tt < 16; tt++)
            pm = fmaxf(pm, Ps[(seg*16 + tt)*64 + rr]);
        red[tid] = pm;
        __syncthreads();
        if (tid < 64) {
            float mnew = fmaxf(fmaxf(fmaxf(red[tid], red[tid+64]),
                                     fmaxf(red[tid+128], red[tid+192])), m_run[tid]);
            alph[tid]  = __expf(m_run[tid] - mnew);
            m_run[tid] = mnew;
        }
        __syncthreads();
        // ---- softmax pass 2 (exp + row sum) ----
        {
            float mn = m_run[rr];
            float psum = 0.f;
#pragma unroll
            for (int tt = 0; tt < 16; tt++) {
                int idx = (seg*16 + tt)*64 + rr;
                float p = __expf(Ps[idx] - mn);
                Ps[idx] = p;
                psum += p;
            }
            red[tid] = psum;
        }
        __syncthreads();
        if (tid < 64)
            l_run[tid] = l_run[tid]*alph[tid]
                       + red[tid] + red[tid+64] + red[tid+128] + red[tid+192];
        // ---- rescale accumulator ----
#pragma unroll
        for (int i = 0; i < 4; i++) {
            float a = alph[(ty<<2)+i];
            acc[i][0]*=a; acc[i][1]*=a; acc[i][2]*=a; acc[i][3]*=a;
        }
        // ---- phase C: O[r][d] += P^T[t][r] * V[t][d] ----
#pragma unroll 16
        for (int t = 0; t < 64; t++) {
            float4 pv = *(const float4*)&Ps[t*64 + (ty<<2)];
            float4 vv = *(const float4*)&KVs[t*64 + (tx<<2)];
            acc[0][0]+=pv.x*vv.x; acc[0][1]+=pv.x*vv.y; acc[0][2]+=pv.x*vv.z; acc[0][3]+=pv.x*vv.w;
            acc[1][0]+=pv.y*vv.x; acc[1][1]+=pv.y*vv.y; acc[1][2]+=pv.y*vv.z; acc[1][3]+=pv.y*vv.w;
            acc[2][0]+=pv.z*vv.x; acc[2][1]+=pv.z*vv.y; acc[2][2]+=pv.z*vv.z; acc[2][3]+=pv.z*vv.w;
            acc[3][0]+=pv.w*vv.x; acc[3][1]+=pv.w*vv.y; acc[3][2]+=pv.w*vv.z; acc[3][3]+=pv.w*vv.w;
        }
        __syncthreads();
    }

    // ---- epilogue: normalize, write hf[b][s][head*64+d] ----
#pragma unroll
    for (int i = 0; i < 4; i++) {
        int r = (ty<<2) + i;
        float invl = 1.f / l_run[r];
        float4 o = make_float4(acc[i][0]*invl, acc[i][1]*invl,
                               acc[i][2]*invl, acc[i][3]*invl);
        *(float4*)(g_hf + (size_t)(b*NS + (qt<<6) + r)*NC + h*HD + (tx<<2)) = o;
    }
}

// ============================================================
// launch
// ============================================================
extern "C" void kernel_launch(void* const* d_in, const int* in_sizes, int n_in,
                              void* d_out, int out_size) {
    const float* x      = (const float*)d_in[0];
    const float* gns    = (const float*)d_in[1];
    const float* gnb    = (const float*)d_in[2];
    const float* qkv_w  = (const float*)d_in[3];
    const float* qkv_b  = (const float*)d_in[4];
    const float* proj_w = (const float*)d_in[5];
    const float* proj_b = (const float*)d_in[6];
    const float* inl_w  = (const float*)d_in[7];
    const float* inl_b  = (const float*)d_in[8];
    float* out = (float*)d_out;

    float *h_p, *hf_p, *hf2_p;
    cudaGetSymbolAddress((void**)&h_p,  g_h);
    cudaGetSymbolAddress((void**)&hf_p, g_hf);
    cudaGetSymbolAddress((void**)&hf2_p, g_hf2);

    const int attn_smem = 12736 * 4;  // 50944 B
    cudaFuncSetAttribute((const void*)attn_kernel,
                         cudaFuncAttributeMaxDynamicSharedMemorySize, attn_smem);

    groupnorm_kernel<<<64, 256>>>(x, gns, gnb);
    gemm_kernel<0><<<dim3(24, 128), 256>>>(h_p, qkv_w, qkv_b, nullptr, nullptr);
    attn_kernel<<<dim3(16, 8, 8), 256, attn_smem>>>();
    gemm_kernel<1><<<dim3(8, 128), 256>>>(hf_p,  inl_w, inl_b, hf_p,  hf2_p);
    gemm_kernel<1><<<dim3(8, 128), 256>>>(hf2_p, inl_w, inl_b, hf2_p, hf_p);
    gemm_kernel<1><<<dim3(8, 128), 256>>>(hf_p,  inl_w, inl_b, hf_p,  hf2_p);
    gemm_kernel<2><<<dim3(8, 128), 256>>>(hf2_p, proj_w, proj_b, x, out);
}

// round 2
// speedup vs baseline: 1.2840x; 1.2840x over previous
#include <cuda_runtime.h>
#include <math.h>

#define NB 8
#define NC 512
#define NS 1024
#define NHD 8
#define HD 64

// ---- scratch (static __device__, no allocs) ----
__device__ float g_h  [NB*NS*NC];        // groupnorm out, [B,S,C]
__device__ float g_q  [NB*NHD*NS*HD];    // [B,nh,S,hd]
__device__ float g_kk [NB*NHD*NS*HD];
__device__ float g_v  [NB*NHD*NS*HD];
__device__ float g_hf [NB*NS*NC];        // [B,S,C]
__device__ float g_hf2[NB*NS*NC];

// ============================================================
// GroupNorm: one block per (b, group).
// ============================================================
__global__ void groupnorm_kernel(const float* __restrict__ x,
                                 const float* __restrict__ gns,
                                 const float* __restrict__ gnb) {
    int b = blockIdx.x >> 3;
    int g = blockIdx.x & 7;
    const float* xp = x + (size_t)(b*NC + g*64) * NS;
    int tid = threadIdx.x;
    float s1 = 0.f, s2 = 0.f;
    for (int i = tid; i < 64*NS; i += 256) {
        float v = xp[i];
        s1 += v; s2 += v*v;
    }
    __shared__ float r1[256], r2[256];
    __shared__ float sm_mean, sm_inv;
    r1[tid] = s1; r2[tid] = s2;
    __syncthreads();
    for (int o = 128; o > 0; o >>= 1) {
        if (tid < o) { r1[tid] += r1[tid+o]; r2[tid] += r2[tid+o]; }
        __syncthreads();
    }
    if (tid == 0) {
        float mean = r1[0] * (1.f/65536.f);
        float var  = r2[0] * (1.f/65536.f) - mean*mean;
        sm_mean = mean;
        sm_inv  = rsqrtf(var + 1e-5f);
    }
    __syncthreads();
    float mean = sm_mean, inv = sm_inv;
    for (int i = tid; i < 64*NS; i += 256) {
        int cl = i >> 10, sp = i & 1023;
        int c = g*64 + cl;
        float v = (xp[i] - mean) * inv * gns[c] + gnb[c];
        g_h[(size_t)(b*NS + sp)*NC + c] = v;
    }
}

// ============================================================
// GEMM: C[M,N] = A[M,512] @ W[N,512]^T  (+ epilogue)
// 128x128 tile, BK=8, 256 threads, 8x8 micro-tile (split frags),
// double-buffered smem.
// MODE 0: qkv scatter  MODE 1: INL tanh step  MODE 2: proj+residual
// ============================================================
template<int MODE>
__global__ void __launch_bounds__(256, 2)
gemm_kernel(const float* __restrict__ A,
            const float* __restrict__ W,
            const float* __restrict__ bias,
            const float* __restrict__ addsrc,
            float* __restrict__ out)
{
    __shared__ float As[2][8][128];
    __shared__ float Ws[2][8][128];
    int tid = threadIdx.x;
    int tx = tid & 15, ty = tid >> 4;
    int n0 = blockIdx.x << 7;
    int m0 = blockIdx.y << 7;
    int lrow = tid >> 1;           // 0..127
    int lk   = (tid & 1) << 2;     // 0 or 4
    const float* Ap = A + (size_t)(m0 + lrow) * NC + lk;
    const float* Wp = W + (size_t)(n0 + lrow) * NC + lk;
    float acc[8][8] = {};

    // stage 0
    {
        float4 av = *(const float4*)Ap;
        float4 wv = *(const float4*)Wp;
        As[0][lk+0][lrow]=av.x; As[0][lk+1][lrow]=av.y;
        As[0][lk+2][lrow]=av.z; As[0][lk+3][lrow]=av.w;
        Ws[0][lk+0][lrow]=wv.x; Ws[0][lk+1][lrow]=wv.y;
        Ws[0][lk+2][lrow]=wv.z; Ws[0][lk+3][lrow]=wv.w;
    }
    __syncthreads();

    int buf = 0;
    for (int kt = 8; kt <= NC; kt += 8) {
        float4 av2, wv2;
        bool more = (kt < NC);
        if (more) {
            av2 = *(const float4*)(Ap + kt);
            wv2 = *(const float4*)(Wp + kt);
        }
#pragma unroll
        for (int k = 0; k < 8; k++) {
            float4 a0 = *(const float4*)&As[buf][k][ty<<2];
            float4 a1 = *(const float4*)&As[buf][k][64 + (ty<<2)];
            float4 b0 = *(const float4*)&Ws[buf][k][tx<<2];
            float4 b1 = *(const float4*)&Ws[buf][k][64 + (tx<<2)];
            float a_[8] = {a0.x,a0.y,a0.z,a0.w,a1.x,a1.y,a1.z,a1.w};
            float b_[8] = {b0.x,b0.y,b0.z,b0.w,b1.x,b1.y,b1.z,b1.w};
#pragma unroll
            for (int i = 0; i < 8; i++)
#pragma unroll
                for (int j = 0; j < 8; j++)
                    acc[i][j] += a_[i] * b_[j];
        }
        if (more) {
            buf ^= 1;
            As[buf][lk+0][lrow]=av2.x; As[buf][lk+1][lrow]=av2.y;
            As[buf][lk+2][lrow]=av2.z; As[buf][lk+3][lrow]=av2.w;
            Ws[buf][lk+0][lrow]=wv2.x; Ws[buf][lk+1][lrow]=wv2.y;
            Ws[buf][lk+2][lrow]=wv2.z; Ws[buf][lk+3][lrow]=wv2.w;
            __syncthreads();
        }
    }

    // epilogue: i -> m, halves; j -> n, halves
#pragma unroll
    for (int i = 0; i < 8; i++) {
        int m = m0 + ((i < 4) ? ((ty<<2) + i) : (64 + (ty<<2) + i - 4));
#pragma unroll
        for (int half = 0; half < 2; half++) {
            int nb = n0 + half*64 + (tx<<2);
            float v0 = acc[i][half*4+0] + bias[nb+0];
            float v1 = acc[i][half*4+1] + bias[nb+1];
            float v2 = acc[i][half*4+2] + bias[nb+2];
            float v3 = acc[i][half*4+3] + bias[nb+3];
            if (MODE == 0) {
                int b = m >> 10, sp = m & 1023;
                int which = nb >> 9, oo = nb & 511;
                int head = oo >> 6, d = oo & 63;
                float* dst = (which == 0) ? g_q : (which == 1) ? g_kk : g_v;
                *(float4*)(dst + (size_t)((b*NHD + head)*NS + sp)*HD + d) =
                    make_float4(v0, v1, v2, v3);
            } else if (MODE == 1) {
                size_t idx = (size_t)m*NC + nb;
                float4 src = *(const float4*)(addsrc + idx);
                *(float4*)(out + idx) = make_float4(
                    src.x + 0.1f*tanhf(v0), src.y + 0.1f*tanhf(v1),
                    src.z + 0.1f*tanhf(v2), src.w + 0.1f*tanhf(v3));
            } else {
                int b = m >> 10, sp = m & 1023;
                size_t base = (size_t)(b*NC + nb)*NS + sp;
                out[base       ] = addsrc[base       ] + v0;
                out[base +   NS] = addsrc[base +   NS] + v1;
                out[base + 2*NS] = addsrc[base + 2*NS] + v2;
                out[base + 3*NS] = addsrc[base + 3*NS] + v3;
            }
        }
    }
}

// ============================================================
// Flash attention: one CTA per (qtile=128 rows, head, batch).
// Smem: QsT[64][128] | KVs (K^T [64][128] then V [128][64]) |
//       Ps [128 t][128 r] | stats
// ============================================================
__global__ void __launch_bounds__(256, 1) attn_kernel() {
    extern __shared__ float sm[];
    float* QsT   = sm;             // [64][128], pre-scaled by 1/8
    float* KVs   = sm + 8192;      // K: [64 d][128 t] ; V: [128 t][64 d]
    float* Ps    = sm + 16384;     // [128 t][128 r]
    float* m_run = sm + 32768;     // [128]
    float* l_run = m_run + 128;
    float* alph  = l_run + 128;
    float* red   = alph + 128;     // [256]

    int tid = threadIdx.x;
    int tx = tid & 15, ty = tid >> 4;
    int qt = blockIdx.x, h = blockIdx.y, b = blockIdx.z;
    const float* Qb = g_q  + (size_t)((b*NHD + h)*NS + (qt<<7)) * HD;
    const float* Kb = g_kk + (size_t)(b*NHD + h)*NS*HD;
    const float* Vb = g_v  + (size_t)(b*NHD + h)*NS*HD;

    // load Q transposed + scaled: QsT[d][r]
    {
        int r = tid & 127, dg = tid >> 7;
#pragma unroll
        for (int it = 0; it < 8; it++) {
            int d0 = dg*32 + it*4;
            float4 v = *(const float4*)(Qb + r*HD + d0);
            QsT[(d0+0)*128 + r] = v.x * 0.125f;
            QsT[(d0+1)*128 + r] = v.y * 0.125f;
            QsT[(d0+2)*128 + r] = v.z * 0.125f;
            QsT[(d0+3)*128 + r] = v.w * 0.125f;
        }
    }
    if (tid < 128) { m_run[tid] = -1e30f; l_run[tid] = 0.f; }
    float acc[8][4] = {};   // O accumulator: 8 r (split) x 4 d
    __syncthreads();

    int seg = tid >> 7;      // softmax: 2 threads per row r
    int rr  = tid & 127;
    int dcg = tid >> 4;      // phase C: d group (0..15)
    // phase C r groups = tx (same split as phase A r)

    for (int kt = 0; kt < 8; kt++) {
        int t0g = kt << 7;
        // ---- load K transposed: KVs[d][t] ----
        {
            int t = tid & 127, dg = tid >> 7;
#pragma unroll
            for (int it = 0; it < 8; it++) {
                int d0 = dg*32 + it*4;
                float4 v = *(const float4*)(Kb + (size_t)(t0g + t)*HD + d0);
                KVs[(d0+0)*128 + t] = v.x;
                KVs[(d0+1)*128 + t] = v.y;
                KVs[(d0+2)*128 + t] = v.z;
                KVs[(d0+3)*128 + t] = v.w;
            }
        }
        __syncthreads();
        // ---- phase A: S^T[t][r] = sum_d K^T[d][t] * Q^T[d][r] ----
        {
            float sc[8][8] = {};
#pragma unroll 8
            for (int d = 0; d < 64; d++) {
                float4 ka = *(const float4*)&KVs[d*128 + (ty<<2)];
                float4 kb = *(const float4*)&KVs[d*128 + 64 + (ty<<2)];
                float4 qa = *(const float4*)&QsT[d*128 + (tx<<2)];
                float4 qb = *(const float4*)&QsT[d*128 + 64 + (tx<<2)];
                float k_[8] = {ka.x,ka.y,ka.z,ka.w,kb.x,kb.y,kb.z,kb.w};
                float q_[8] = {qa.x,qa.y,qa.z,qa.w,qb.x,qb.y,qb.z,qb.w};
#pragma unroll
                for (int i = 0; i < 8; i++)
#pragma unroll
                    for (int j = 0; j < 8; j++)
                        sc[i][j] += k_[i] * q_[j];
            }
#pragma unroll
            for (int i = 0; i < 8; i++) {
                int t = (i < 4) ? ((ty<<2) + i) : (64 + (ty<<2) + i - 4);
                *(float4*)&Ps[t*128 + (tx<<2)] =
                    make_float4(sc[i][0], sc[i][1], sc[i][2], sc[i][3]);
                *(float4*)&Ps[t*128 + 64 + (tx<<2)] =
                    make_float4(sc[i][4], sc[i][5], sc[i][6], sc[i][7]);
            }
        }
        __syncthreads();
        // ---- load V (linear) into KVs as [t][d] + softmax pass 1 ----
        {
            const float4* src  = (const float4*)(Vb + (size_t)t0g*HD);
            float4* dst4 = (float4*)KVs;
#pragma unroll
            for (int it = 0; it < 8; it++)
                dst4[tid + it*256] = src[tid + it*256];
        }
        {
            float pm = -1e30f;
#pragma unroll
            for (int tt = 0; tt < 64; tt++)
                pm = fmaxf(pm, Ps[(seg*64 + tt)*128 + rr]);
            red[tid] = pm;
        }
        __syncthreads();
        if (tid < 128) {
            float mnew = fmaxf(fmaxf(red[tid], red[tid+128]), m_run[tid]);
            alph[tid]  = __expf(m_run[tid] - mnew);
            m_run[tid] = mnew;
        }
        __syncthreads();
        // ---- softmax pass 2 (exp + partial sums) ----
        {
            float mn = m_run[rr];
            float psum = 0.f;
#pragma unroll
            for (int tt = 0; tt < 64; tt++) {
                int idx = (seg*64 + tt)*128 + rr;
                float p = __expf(Ps[idx] - mn);
                Ps[idx] = p;
                psum += p;
            }
            red[tid] = psum;
        }
        __syncthreads();
        if (tid < 128)
            l_run[tid] = l_run[tid]*alph[tid] + red[tid] + red[tid+128];
        // ---- rescale accumulator ----
#pragma unroll
        for (int j = 0; j < 8; j++) {
            int r = (j < 4) ? ((tx<<2) + j) : (64 + (tx<<2) + j - 4);
            float a = alph[r];
            acc[j][0]*=a; acc[j][1]*=a; acc[j][2]*=a; acc[j][3]*=a;
        }
        // ---- phase C: O[r][d] += P^T[t][r] * V[t][d] ----
#pragma unroll 8
        for (int t = 0; t < 128; t++) {
            float4 pa = *(const float4*)&Ps[t*128 + (tx<<2)];
            float4 pb = *(const float4*)&Ps[t*128 + 64 + (tx<<2)];
            float4 vv = *(const float4*)&KVs[t*64 + (dcg<<2)];
            float p_[8] = {pa.x,pa.y,pa.z,pa.w,pb.x,pb.y,pb.z,pb.w};
            acc[0][0]+=p_[0]*vv.x; acc[0][1]+=p_[0]*vv.y; acc[0][2]+=p_[0]*vv.z; acc[0][3]+=p_[0]*vv.w;
            acc[1][0]+=p_[1]*vv.x; acc[1][1]+=p_[1]*vv.y; acc[1][2]+=p_[1]*vv.z; acc[1][3]+=p_[1]*vv.w;
            acc[2][0]+=p_[2]*vv.x; acc[2][1]+=p_[2]*vv.y; acc[2][2]+=p_[2]*vv.z; acc[2][3]+=p_[2]*vv.w;
            acc[3][0]+=p_[3]*vv.x; acc[3][1]+=p_[3]*vv.y; acc[3][2]+=p_[3]*vv.z; acc[3][3]+=p_[3]*vv.w;
            acc[4][0]+=p_[4]*vv.x; acc[4][1]+=p_[4]*vv.y; acc[4][2]+=p_[4]*vv.z; acc[4][3]+=p_[4]*vv.w;
            acc[5][0]+=p_[5]*vv.x; acc[5][1]+=p_[5]*vv.y; acc[5][2]+=p_[5]*vv.z; acc[5][3]+=p_[5]*vv.w;
            acc[6][0]+=p_[6]*vv.x; acc[6][1]+=p_[6]*vv.y; acc[6][2]+=p_[6]*vv.z; acc[6][3]+=p_[6]*vv.w;
            acc[7][0]+=p_[7]*vv.x; acc[7][1]+=p_[7]*vv.y; acc[7][2]+=p_[7]*vv.z; acc[7][3]+=p_[7]*vv.w;
        }
        __syncthreads();
    }

    // ---- epilogue: normalize, write hf[b][s][h*64+d] ----
#pragma unroll
    for (int j = 0; j < 8; j++) {
        int r = (j < 4) ? ((tx<<2) + j) : (64 + (tx<<2) + j - 4);
        float invl = 1.f / l_run[r];
        float4 o = make_float4(acc[j][0]*invl, acc[j][1]*invl,
                               acc[j][2]*invl, acc[j][3]*invl);
        *(float4*)(g_hf + (size_t)(b*NS + (qt<<7) + r)*NC + h*HD + (dcg<<2)) = o;
    }
}

// ============================================================
// launch
// ============================================================
extern "C" void kernel_launch(void* const* d_in, const int* in_sizes, int n_in,
                              void* d_out, int out_size) {
    const float* x      = (const float*)d_in[0];
    const float* gns    = (const float*)d_in[1];
    const float* gnb    = (const float*)d_in[2];
    const float* qkv_w  = (const float*)d_in[3];
    const float* qkv_b  = (const float*)d_in[4];
    const float* proj_w = (const float*)d_in[5];
    const float* proj_b = (const float*)d_in[6];
    const float* inl_w  = (const float*)d_in[7];
    const float* inl_b  = (const float*)d_in[8];
    float* out = (float*)d_out;

    float *h_p, *hf_p, *hf2_p;
    cudaGetSymbolAddress((void**)&h_p,  g_h);
    cudaGetSymbolAddress((void**)&hf_p, g_hf);
    cudaGetSymbolAddress((void**)&hf2_p, g_hf2);

    const int attn_smem = 33408 * 4;  // 133,632 B
    cudaFuncSetAttribute((const void*)attn_kernel,
                         cudaFuncAttributeMaxDynamicSharedMemorySize, attn_smem);

    groupnorm_kernel<<<64, 256>>>(x, gns, gnb);
    gemm_kernel<0><<<dim3(12, 64), 256>>>(h_p, qkv_w, qkv_b, nullptr, nullptr);
    attn_kernel<<<dim3(8, 8, 8), 256, attn_smem>>>();
    gemm_kernel<1><<<dim3(4, 64), 256>>>(hf_p,  inl_w, inl_b, hf_p,  hf2_p);
    gemm_kernel<1><<<dim3(4, 64), 256>>>(hf2_p, inl_w, inl_b, hf2_p, hf_p);
    gemm_kernel<1><<<dim3(4, 64), 256>>>(hf_p,  inl_w, inl_b, hf_p,  hf2_p);
    gemm_kernel<2><<<dim3(4, 64), 256>>>(hf2_p, proj_w, proj_b, x, out);
}

// round 4
// speedup vs baseline: 1.4922x; 1.1621x over previous
#include <cuda_runtime.h>
#include <cuda_bf16.h>
#include <math.h>
#include <cstdint>

#define NB 8
#define NC 512
#define NS 1024
#define NHD 8
#define HD 64

// ---- scratch (static __device__, no allocs) ----
__device__ __nv_bfloat16 g_h_hi [NB*NS*NC];
__device__ __nv_bfloat16 g_h_lo [NB*NS*NC];
__device__ float g_q  [NB*NHD*NS*HD];
__device__ float g_kk [NB*NHD*NS*HD];
__device__ float g_v  [NB*NHD*NS*HD];
__device__ float g_hf [NB*NS*NC];
__device__ float g_hf2[NB*NS*NC];
__device__ __nv_bfloat16 g_hf_hi [NB*NS*NC];
__device__ __nv_bfloat16 g_hf_lo [NB*NS*NC];
__device__ __nv_bfloat16 g_hf2_hi[NB*NS*NC];
__device__ __nv_bfloat16 g_hf2_lo[NB*NS*NC];
__device__ __nv_bfloat16 g_wq_hi[3*NC*NC], g_wq_lo[3*NC*NC];
__device__ __nv_bfloat16 g_wi_hi[NC*NC],   g_wi_lo[NC*NC];
__device__ __nv_bfloat16 g_wp_hi[NC*NC],   g_wp_lo[NC*NC];

__device__ __forceinline__ uint32_t smem_u32(const void* p) {
    uint32_t a;
    asm("{ .reg .u64 t; cvta.to.shared.u64 t, %1; cvt.u32.u64 %0, t; }" : "=r"(a) : "l"(p));
    return a;
}
__device__ __forceinline__ void ldsm4(uint32_t& r0, uint32_t& r1, uint32_t& r2,
                                      uint32_t& r3, uint32_t addr) {
    asm volatile("ldmatrix.sync.aligned.m8n8.x4.shared.b16 {%0,%1,%2,%3}, [%4];"
                 : "=r"(r0), "=r"(r1), "=r"(r2), "=r"(r3) : "r"(addr));
}
__device__ __forceinline__ void mma16816(float* d, const uint32_t* a, const uint32_t* b) {
    asm volatile("mma.sync.aligned.m16n8k16.row.col.f32.bf16.bf16.f32 "
        "{%0,%1,%2,%3},{%4,%5,%6,%7},{%8,%9},{%0,%1,%2,%3};"
        : "+f"(d[0]), "+f"(d[1]), "+f"(d[2]), "+f"(d[3])
        : "r"(a[0]), "r"(a[1]), "r"(a[2]), "r"(a[3]), "r"(b[0]), "r"(b[1]));
}

// ============================================================
// weight fp32 -> bf16 hi/lo
// ============================================================
__global__ void cvt_kernel(const float* __restrict__ src,
                           __nv_bfloat16* __restrict__ hi,
                           __nv_bfloat16* __restrict__ lo, int n) {
    int i = blockIdx.x * 256 + threadIdx.x;
    if (i < n) {
        float v = src[i];
        __nv_bfloat16 h = __float2bfloat16(v);
        hi[i] = h;
        lo[i] = __float2bfloat16(v - __bfloat162float(h));
    }
}

// ============================================================
// GroupNorm -> h (bf16 hi/lo, [B,S,C])
// ============================================================
__global__ void groupnorm_kernel(const float* __restrict__ x,
                                 const float* __restrict__ gns,
                                 const float* __restrict__ gnb) {
    int b = blockIdx.x >> 3;
    int g = blockIdx.x & 7;
    const float* xp = x + (size_t)(b*NC + g*64) * NS;
    int tid = threadIdx.x;
    float s1 = 0.f, s2 = 0.f;
    for (int i = tid; i < 64*NS; i += 256) {
        float v = xp[i];
        s1 += v; s2 += v*v;
    }
    __shared__ float r1[256], r2[256];
    __shared__ float sm_mean, sm_inv;
    r1[tid] = s1; r2[tid] = s2;
    __syncthreads();
    for (int o = 128; o > 0; o >>= 1) {
        if (tid < o) { r1[tid] += r1[tid+o]; r2[tid] += r2[tid+o]; }
        __syncthreads();
    }
    if (tid == 0) {
        float mean = r1[0] * (1.f/65536.f);
        float var  = r2[0] * (1.f/65536.f) - mean*mean;
        sm_mean = mean;
        sm_inv  = rsqrtf(var + 1e-5f);
    }
    __syncthreads();
    float mean = sm_mean, inv = sm_inv;
    for (int i = tid; i < 64*NS; i += 256) {
        int cl = i >> 10, sp = i & 1023;
        int c = g*64 + cl;
        float v = (xp[i] - mean) * inv * gns[c] + gnb[c];
        size_t idx = (size_t)(b*NS + sp)*NC + c;
        __nv_bfloat16 h = __float2bfloat16(v);
        g_h_hi[idx] = h;
        g_h_lo[idx] = __float2bfloat16(v - __bfloat162float(h));
    }
}

// ============================================================
// mma.sync split-bf16 GEMM: C[M,N] = A[M,512] @ W[N,512]^T
// D = Ah*Bh + Al*Bh + Ah*Bl, fp32 accum.
// CTA 128x128, BK=64, 8 warps 2x4 (warp tile 64x32), dbl-buffered.
// MODE 0: qkv scatter  MODE 1: INL tanh step  MODE 2: proj+residual
// ============================================================
#define PITCH_B 144                 // 72 bf16 per row (16B-aligned)
#define STG_AL  (128*PITCH_B)       // 18432
#define STG_B   (2*128*PITCH_B)
#define STG_BL  (3*128*PITCH_B)
#define STAGE_BYTES (4*128*PITCH_B) // 73728
#define GEMM_SMEM (2*STAGE_BYTES)   // 147456

template<int MODE>
__global__ void __launch_bounds__(256, 1)
mm_gemm(const __nv_bfloat16* __restrict__ Ah, const __nv_bfloat16* __restrict__ Al,
        const __nv_bfloat16* __restrict__ Wh, const __nv_bfloat16* __restrict__ Wl,
        const float* __restrict__ bias,
        const float* __restrict__ addsrc, float* __restrict__ out,
        __nv_bfloat16* __restrict__ ohi, __nv_bfloat16* __restrict__ olo)
{
    extern __shared__ char smem[];
    uint32_t sb = smem_u32(smem);
    int tid = threadIdx.x, lane = tid & 31, wid = tid >> 5;
    int wm = wid >> 2, wn = wid & 3;
    int n0 = blockIdx.x << 7, m0 = blockIdx.y << 7;

    float D[4][4][4] = {};

    auto load_stage = [&](int s, int bb) {
        int k0 = s << 6;
        char* base = smem + bb*STAGE_BYTES;
#pragma unroll
        for (int it = 0; it < 8; it++) {
            int chunk = tid + it*256;          // 2048 chunks of 4 bf16
            int r = chunk >> 4, c = chunk & 15;
            size_t ga = (size_t)(m0 + r)*NC + k0 + c*4;
            size_t gb = (size_t)(n0 + r)*NC + k0 + c*4;
            uint32_t so = r*PITCH_B + c*8;
            *(uint2*)(base + so)          = *(const uint2*)(Ah + ga);
            *(uint2*)(base + STG_AL + so) = *(const uint2*)(Al + ga);
            *(uint2*)(base + STG_B  + so) = *(const uint2*)(Wh + gb);
            *(uint2*)(base + STG_BL + so) = *(const uint2*)(Wl + gb);
        }
    };

    // fragment base addresses (stage-relative)
    uint32_t aOff = (uint32_t)(wm*64 + (lane & 15))*PITCH_B + (lane >> 4)*16;
    uint32_t bOff = (uint32_t)STG_B
                  + (uint32_t)(wn*32 + ((lane >> 4) & 1)*8 + (lane & 7))*PITCH_B
                  + ((lane >> 3) & 1)*16;

    load_stage(0, 0);
    __syncthreads();

    int buf = 0;
    for (int s = 0; s < 8; s++) {
        if (s < 7) load_stage(s + 1, buf ^ 1);
        uint32_t base = sb + buf*STAGE_BYTES;
#pragma unroll
        for (int ks = 0; ks < 4; ks++) {
            uint32_t ah[4][4], al[4][4], bh[2][4], bl[2][4];
#pragma unroll
            for (int i = 0; i < 4; i++) {
                uint32_t adr = base + aOff + i*(16*PITCH_B) + ks*32;
                ldsm4(ah[i][0], ah[i][1], ah[i][2], ah[i][3], adr);
                ldsm4(al[i][0], al[i][1], al[i][2], al[i][3], adr + STG_AL);
            }
#pragma unroll
            for (int j2 = 0; j2 < 2; j2++) {
                uint32_t adr = base + bOff + j2*(16*PITCH_B) + ks*32;
                ldsm4(bh[j2][0], bh[j2][1], bh[j2][2], bh[j2][3], adr);
                ldsm4(bl[j2][0], bl[j2][1], bl[j2][2], bl[j2][3], adr + STG_AL);
            }
#pragma unroll
            for (int i = 0; i < 4; i++)
#pragma unroll
                for (int j2 = 0; j2 < 2; j2++) {
                    mma16816(D[i][2*j2],   ah[i], &bh[j2][0]);
                    mma16816(D[i][2*j2],   al[i], &bh[j2][0]);
                    mma16816(D[i][2*j2],   ah[i], &bl[j2][0]);
                    mma16816(D[i][2*j2+1], ah[i], &bh[j2][2]);
                    mma16816(D[i][2*j2+1], al[i], &bh[j2][2]);
                    mma16816(D[i][2*j2+1], ah[i], &bl[j2][2]);
                }
        }
        __syncthreads();
        buf ^= 1;
    }

    // ---- epilogue ----
    int g = lane >> 2, tig = lane & 3;
#pragma unroll
    for (int i = 0; i < 4; i++) {
#pragma unroll
        for (int j = 0; j < 4; j++) {
            int Cn = n0 + wn*32 + j*8 + tig*2;
            float b0 = bias[Cn], b1 = bias[Cn+1];
#pragma unroll
            for (int hr = 0; hr < 2; hr++) {
                int R = m0 + wm*64 + i*16 + g + hr*8;
                float v0 = D[i][j][hr*2+0] + b0;
                float v1 = D[i][j][hr*2+1] + b1;
                if (MODE == 0) {
                    int b = R >> 10, sp = R & 1023;
                    int which = Cn >> 9, head = (Cn >> 6) & 7, d = Cn & 63;
                    float* dst = (which == 0) ? g_q : (which == 1) ? g_kk : g_v;
                    *(float2*)(dst + (size_t)((b*NHD + head)*NS + sp)*HD + d) =
                        make_float2(v0, v1);
                } else if (MODE == 1) {
                    size_t idx = (size_t)R*NC + Cn;
                    float2 s2 = *(const float2*)(addsrc + idx);
                    float r0 = s2.x + 0.1f*tanhf(v0);
                    float r1 = s2.y + 0.1f*tanhf(v1);
                    *(float2*)(out + idx) = make_float2(r0, r1);
                    __nv_bfloat16 h0 = __float2bfloat16(r0);
                    __nv_bfloat16 h1 = __float2bfloat16(r1);
                    __nv_bfloat162 hp; hp.x = h0; hp.y = h1;
                    *(__nv_bfloat162*)(ohi + idx) = hp;
                    __nv_bfloat162 lp;
                    lp.x = __float2bfloat16(r0 - __bfloat162float(h0));
                    lp.y = __float2bfloat16(r1 - __bfloat162float(h1));
                    *(__nv_bfloat162*)(olo + idx) = lp;
                } else {
                    int b = R >> 10, sp = R & 1023;
                    size_t basei = (size_t)(b*NC + Cn)*NS + sp;
                    out[basei     ] = addsrc[basei     ] + v0;
                    out[basei + NS] = addsrc[basei + NS] + v1;
                }
            }
        }
    }
}

// ============================================================
// Flash attention (SIMT fp32; epilogue emits fp32 + bf16 hi/lo)
// ============================================================
__global__ void __launch_bounds__(256, 1) attn_kernel() {
    extern __shared__ float sm[];
    float* QsT   = sm;
    float* KVs   = sm + 8192;
    float* Ps    = sm + 16384;
    float* m_run = sm + 32768;
    float* l_run = m_run + 128;
    float* alph  = l_run + 128;
    float* red   = alph + 128;

    int tid = threadIdx.x;
    int tx = tid & 15, ty = tid >> 4;
    int qt = blockIdx.x, h = blockIdx.y, b = blockIdx.z;
    const float* Qb = g_q  + (size_t)((b*NHD + h)*NS + (qt<<7)) * HD;
    const float* Kb = g_kk + (size_t)(b*NHD + h)*NS*HD;
    const float* Vb = g_v  + (size_t)(b*NHD + h)*NS*HD;

    {
        int r = tid & 127, dg = tid >> 7;
#pragma unroll
        for (int it = 0; it < 8; it++) {
            int d0 = dg*32 + it*4;
            float4 v = *(const float4*)(Qb + r*HD + d0);
            QsT[(d0+0)*128 + r] = v.x * 0.125f;
            QsT[(d0+1)*128 + r] = v.y * 0.125f;
            QsT[(d0+2)*128 + r] = v.z * 0.125f;
            QsT[(d0+3)*128 + r] = v.w * 0.125f;
        }
    }
    if (tid < 128) { m_run[tid] = -1e30f; l_run[tid] = 0.f; }
    float acc[8][4] = {};
    __syncthreads();

    int seg = tid >> 7;
    int rr  = tid & 127;
    int dcg = tid >> 4;

    for (int kt = 0; kt < 8; kt++) {
        int t0g = kt << 7;
        {
            int t = tid & 127, dg = tid >> 7;
#pragma unroll
            for (int it = 0; it < 8; it++) {
                int d0 = dg*32 + it*4;
                float4 v = *(const float4*)(Kb + (size_t)(t0g + t)*HD + d0);
                KVs[(d0+0)*128 + t] = v.x;
                KVs[(d0+1)*128 + t] = v.y;
                KVs[(d0+2)*128 + t] = v.z;
                KVs[(d0+3)*128 + t] = v.w;
            }
        }
        __syncthreads();
        {
            float sc[8][8] = {};
#pragma unroll 8
            for (int d = 0; d < 64; d++) {
                float4 ka = *(const float4*)&KVs[d*128 + (ty<<2)];
                float4 kb = *(const float4*)&KVs[d*128 + 64 + (ty<<2)];
                float4 qa = *(const float4*)&QsT[d*128 + (tx<<2)];
                float4 qb = *(const float4*)&QsT[d*128 + 64 + (tx<<2)];
                float k_[8] = {ka.x,ka.y,ka.z,ka.w,kb.x,kb.y,kb.z,kb.w};
                float q_[8] = {qa.x,qa.y,qa.z,qa.w,qb.x,qb.y,qb.z,qb.w};
#pragma unroll
                for (int i = 0; i < 8; i++)
#pragma unroll
                    for (int j = 0; j < 8; j++)
                        sc[i][j] += k_[i] * q_[j];
            }
#pragma unroll
            for (int i = 0; i < 8; i++) {
                int t = (i < 4) ? ((ty<<2) + i) : (64 + (ty<<2) + i - 4);
                *(float4*)&Ps[t*128 + (tx<<2)] =
                    make_float4(sc[i][0], sc[i][1], sc[i][2], sc[i][3]);
                *(float4*)&Ps[t*128 + 64 + (tx<<2)] =
                    make_float4(sc[i][4], sc[i][5], sc[i][6], sc[i][7]);
            }
        }
        __syncthreads();
        {
            const float4* src  = (const float4*)(Vb + (size_t)t0g*HD);
            float4* dst4 = (float4*)KVs;
#pragma unroll
            for (int it = 0; it < 8; it++)
                dst4[tid + it*256] = src[tid + it*256];
        }
        {
            float pm = -1e30f;
#pragma unroll
            for (int tt = 0; tt < 64; tt++)
                pm = fmaxf(pm, Ps[(seg*64 + tt)*128 + rr]);
            red[tid] = pm;
        }
        __syncthreads();
        if (tid < 128) {
            float mnew = fmaxf(fmaxf(red[tid], red[tid+128]), m_run[tid]);
            alph[tid]  = __expf(m_run[tid] - mnew);
            m_run[tid] = mnew;
        }
        __syncthreads();
        {
            float mn = m_run[rr];
            float psum = 0.f;
#pragma unroll
            for (int tt = 0; tt < 64; tt++) {
                int idx = (seg*64 + tt)*128 + rr;
                float p = __expf(Ps[idx] - mn);
                Ps[idx] = p;
                psum += p;
            }
            red[tid] = psum;
        }
        __syncthreads();
        if (tid < 128)
            l_run[tid] = l_run[tid]*alph[tid] + red[tid] + red[tid+128];
#pragma unroll
        for (int j = 0; j < 8; j++) {
            int r = (j < 4) ? ((tx<<2) + j) : (64 + (tx<<2) + j - 4);
            float a = alph[r];
            acc[j][0]*=a; acc[j][1]*=a; acc[j][2]*=a; acc[j][3]*=a;
        }
#pragma unroll 8
        for (int t = 0; t < 128; t++) {
            float4 pa = *(const float4*)&Ps[t*128 + (tx<<2)];
            float4 pb = *(const float4*)&Ps[t*128 + 64 + (tx<<2)];
            float4 vv = *(const float4*)&KVs[t*64 + (dcg<<2)];
            float p_[8] = {pa.x,pa.y,pa.z,pa.w,pb.x,pb.y,pb.z,pb.w};
#pragma unroll
            for (int j = 0; j < 8; j++) {
                acc[j][0]+=p_[j]*vv.x; acc[j][1]+=p_[j]*vv.y;
                acc[j][2]+=p_[j]*vv.z; acc[j][3]+=p_[j]*vv.w;
            }
        }
        __syncthreads();
    }

#pragma unroll
    for (int j = 0; j < 8; j++) {
        int r = (j < 4) ? ((tx<<2) + j) : (64 + (tx<<2) + j - 4);
        float invl = 1.f / l_run[r];
        float r0 = acc[j][0]*invl, r1 = acc[j][1]*invl;
        float r2 = acc[j][2]*invl, r3 = acc[j][3]*invl;
        size_t off = (size_t)(b*NS + (qt<<7) + r)*NC + h*HD + (dcg<<2);
        *(float4*)(g_hf + off) = make_float4(r0, r1, r2, r3);
        __nv_bfloat16 h0 = __float2bfloat16(r0), h1 = __float2bfloat16(r1);
        __nv_bfloat16 h2 = __float2bfloat16(r2), h3 = __float2bfloat16(r3);
        __nv_bfloat162 hp0; hp0.x = h0; hp0.y = h1;
        __nv_bfloat162 hp1; hp1.x = h2; hp1.y = h3;
        *(__nv_bfloat162*)(g_hf_hi + off)     = hp0;
        *(__nv_bfloat162*)(g_hf_hi + off + 2) = hp1;
        __nv_bfloat162 lp0, lp1;
        lp0.x = __float2bfloat16(r0 - __bfloat162float(h0));
        lp0.y = __float2bfloat16(r1 - __bfloat162float(h1));
        lp1.x = __float2bfloat16(r2 - __bfloat162float(h2));
        lp1.y = __float2bfloat16(r3 - __bfloat162float(h3));
        *(__nv_bfloat162*)(g_hf_lo + off)     = lp0;
        *(__nv_bfloat162*)(g_hf_lo + off + 2) = lp1;
    }
}

// ============================================================
// launch
// ============================================================
extern "C" void kernel_launch(void* const* d_in, const int* in_sizes, int n_in,
                              void* d_out, int out_size) {
    const float* x      = (const float*)d_in[0];
    const float* gns    = (const float*)d_in[1];
    const float* gnb    = (const float*)d_in[2];
    const float* qkv_w  = (const float*)d_in[3];
    const float* qkv_b  = (const float*)d_in[4];
    const float* proj_w = (const float*)d_in[5];
    const float* proj_b = (const float*)d_in[6];
    const float* inl_w  = (const float*)d_in[7];
    const float* inl_b  = (const float*)d_in[8];
    float* out = (float*)d_out;

    __nv_bfloat16 *hh, *hl, *wqh, *wql, *wih, *wil, *wph, *wpl;
    __nv_bfloat16 *hfh, *hfl, *hf2h, *hf2l;
    float *hf, *hf2;
    cudaGetSymbolAddress((void**)&hh,   g_h_hi);
    cudaGetSymbolAddress((void**)&hl,   g_h_lo);
    cudaGetSymbolAddress((void**)&wqh,  g_wq_hi);
    cudaGetSymbolAddress((void**)&wql,  g_wq_lo);
    cudaGetSymbolAddress((void**)&wih,  g_wi_hi);
    cudaGetSymbolAddress((void**)&wil,  g_wi_lo);
    cudaGetSymbolAddress((void**)&wph,  g_wp_hi);
    cudaGetSymbolAddress((void**)&wpl,  g_wp_lo);
    cudaGetSymbolAddress((void**)&hf,   g_hf);
    cudaGetSymbolAddress((void**)&hf2,  g_hf2);
    cudaGetSymbolAddress((void**)&hfh,  g_hf_hi);
    cudaGetSymbolAddress((void**)&hfl,  g_hf_lo);
    cudaGetSymbolAddress((void**)&hf2h, g_hf2_hi);
    cudaGetSymbolAddress((void**)&hf2l, g_hf2_lo);

    const int attn_smem = 33408 * 4;
    cudaFuncSetAttribute((const void*)attn_kernel,
                         cudaFuncAttributeMaxDynamicSharedMemorySize, attn_smem);
    cudaFuncSetAttribute((const void*)mm_gemm<0>,
                         cudaFuncAttributeMaxDynamicSharedMemorySize, GEMM_SMEM);
    cudaFuncSetAttribute((const void*)mm_gemm<1>,
                         cudaFuncAttributeMaxDynamicSharedMemorySize, GEMM_SMEM);
    cudaFuncSetAttribute((const void*)mm_gemm<2>,
                         cudaFuncAttributeMaxDynamicSharedMemorySize, GEMM_SMEM);

    cvt_kernel<<<(3*NC*NC + 255)/256, 256>>>(qkv_w,  wqh, wql, 3*NC*NC);
    cvt_kernel<<<(NC*NC   + 255)/256, 256>>>(inl_w,  wih, wil, NC*NC);
    cvt_kernel<<<(NC*NC   + 255)/256, 256>>>(proj_w, wph, wpl, NC*NC);
    groupnorm_kernel<<<64, 256>>>(x, gns, gnb);

    mm_gemm<0><<<dim3(12, 64), 256, GEMM_SMEM>>>(hh, hl, wqh, wql, qkv_b,
                                                 nullptr, nullptr, nullptr, nullptr);
    attn_kernel<<<dim3(8, 8, 8), 256, attn_smem>>>();
    mm_gemm<1><<<dim3(4, 64), 256, GEMM_SMEM>>>(hfh, hfl, wih, wil, inl_b,
                                                hf, hf2, hf2h, hf2l);
    mm_gemm<1><<<dim3(4, 64), 256, GEMM_SMEM>>>(hf2h, hf2l, wih, wil, inl_b,
                                                hf2, hf, hfh, hfl);
    mm_gemm<1><<<dim3(4, 64), 256, GEMM_SMEM>>>(hfh, hfl, wih, wil, inl_b,
                                                hf, hf2, hf2h, hf2l);
    mm_gemm<2><<<dim3(4, 64), 256, GEMM_SMEM>>>(hf2h, hf2l, wph, wpl, proj_b,
                                                x, out, nullptr, nullptr);
}

// round 5
// speedup vs baseline: 2.7923x; 1.8712x over previous
#include <cuda_runtime.h>
#include <cuda_bf16.h>
#include <math.h>
#include <cstdint>

#define NB 8
#define NC 512
#define NS 1024
#define NHD 8
#define HD 64
#define QSCALE 0.180336540f   // 0.125 * log2(e)

// ---- scratch (static __device__, no allocs) ----
__device__ __nv_bfloat16 g_h_hi [NB*NS*NC];
__device__ __nv_bfloat16 g_h_lo [NB*NS*NC];
__device__ __nv_bfloat16 g_qh[NB*NHD*NS*HD], g_ql[NB*NHD*NS*HD];
__device__ __nv_bfloat16 g_kh[NB*NHD*NS*HD], g_kl[NB*NHD*NS*HD];
__device__ __nv_bfloat16 g_vh[NB*NHD*NS*HD], g_vl[NB*NHD*NS*HD];
__device__ float g_hf [NB*NS*NC];
__device__ float g_hf2[NB*NS*NC];
__device__ __nv_bfloat16 g_hf_hi [NB*NS*NC];
__device__ __nv_bfloat16 g_hf_lo [NB*NS*NC];
__device__ __nv_bfloat16 g_hf2_hi[NB*NS*NC];
__device__ __nv_bfloat16 g_hf2_lo[NB*NS*NC];
__device__ __nv_bfloat16 g_wq_hi[3*NC*NC], g_wq_lo[3*NC*NC];
__device__ __nv_bfloat16 g_wi_hi[NC*NC],   g_wi_lo[NC*NC];
__device__ __nv_bfloat16 g_wp_hi[NC*NC],   g_wp_lo[NC*NC];
__device__ float2 g_part[512];
__device__ float2 g_stat[64];

__device__ __forceinline__ uint32_t smem_u32(const void* p) {
    uint32_t a;
    asm("{ .reg .u64 t; cvta.to.shared.u64 t, %1; cvt.u32.u64 %0, t; }" : "=r"(a) : "l"(p));
    return a;
}
__device__ __forceinline__ void ldsm4(uint32_t& r0, uint32_t& r1, uint32_t& r2,
                                      uint32_t& r3, uint32_t addr) {
    asm volatile("ldmatrix.sync.aligned.m8n8.x4.shared.b16 {%0,%1,%2,%3}, [%4];"
                 : "=r"(r0), "=r"(r1), "=r"(r2), "=r"(r3) : "r"(addr));
}
__device__ __forceinline__ void ldsm4t(uint32_t& r0, uint32_t& r1, uint32_t& r2,
                                       uint32_t& r3, uint32_t addr) {
    asm volatile("ldmatrix.sync.aligned.m8n8.x4.trans.shared.b16 {%0,%1,%2,%3}, [%4];"
                 : "=r"(r0), "=r"(r1), "=r"(r2), "=r"(r3) : "r"(addr));
}
__device__ __forceinline__ void mma16816(float* d, const uint32_t* a, const uint32_t* b) {
    asm volatile("mma.sync.aligned.m16n8k16.row.col.f32.bf16.bf16.f32 "
        "{%0,%1,%2,%3},{%4,%5,%6,%7},{%8,%9},{%0,%1,%2,%3};"
        : "+f"(d[0]), "+f"(d[1]), "+f"(d[2]), "+f"(d[3])
        : "r"(a[0]), "r"(a[1]), "r"(a[2]), "r"(a[3]), "r"(b[0]), "r"(b[1]));
}
__device__ __forceinline__ uint32_t pack_bf2(float a, float b) {
    __nv_bfloat162 t; t.x = __float2bfloat16(a); t.y = __float2bfloat16(b);
    return *(uint32_t*)&t;
}

// ============================================================
// weight fp32 -> bf16 hi/lo
// ============================================================
__global__ void cvt_kernel(const float* __restrict__ src,
                           __nv_bfloat16* __restrict__ hi,
                           __nv_bfloat16* __restrict__ lo, int n) {
    int i = blockIdx.x * 256 + threadIdx.x;
    if (i < n) {
        float v = src[i];
        __nv_bfloat16 h = __float2bfloat16(v);
        hi[i] = h;
        lo[i] = __float2bfloat16(v - __bfloat162float(h));
    }
}

// ============================================================
// GroupNorm, 3-stage
// ============================================================
__global__ void gn_stats1(const float* __restrict__ x) {
    int bg = blockIdx.x >> 3, chunk = blockIdx.x & 7;
    const float4* xp = (const float4*)(x + (size_t)bg*65536 + chunk*8192);
    int tid = threadIdx.x;
    float s1 = 0.f, s2 = 0.f;
#pragma unroll
    for (int it = 0; it < 8; it++) {
        float4 v = xp[tid + it*256];
        s1 += v.x + v.y + v.z + v.w;
        s2 += v.x*v.x + v.y*v.y + v.z*v.z + v.w*v.w;
    }
    __shared__ float r1[256], r2[256];
    r1[tid] = s1; r2[tid] = s2;
    __syncthreads();
    for (int o = 128; o > 0; o >>= 1) {
        if (tid < o) { r1[tid] += r1[tid+o]; r2[tid] += r2[tid+o]; }
        __syncthreads();
    }
    if (tid == 0) g_part[blockIdx.x] = make_float2(r1[0], r2[0]);
}
__global__ void gn_stats2() {
    int g = threadIdx.x;   // 0..63
    float s1 = 0.f, s2 = 0.f;
#pragma unroll
    for (int i = 0; i < 8; i++) {
        float2 p = g_part[g*8 + i];
        s1 += p.x; s2 += p.y;
    }
    float mean = s1 * (1.f/65536.f);
    float var  = s2 * (1.f/65536.f) - mean*mean;
    g_stat[g] = make_float2(mean, rsqrtf(var + 1e-5f));
}
// tiled transpose apply: block = 64c x 64sp tile
__global__ void gn_apply(const float* __restrict__ x,
                         const float* __restrict__ gns,
                         const float* __restrict__ gnb) {
    __shared__ float tile[64][65];
    int sp0 = blockIdx.x << 6, c0 = blockIdx.y << 6, b = blockIdx.z;
    int tid = threadIdx.x;
    float2 st = g_stat[b*8 + blockIdx.y];   // c-tile == group (both 64 wide)
    int cl_l = tid >> 6, sp_l = tid & 63;
#pragma unroll
    for (int it = 0; it < 16; it++) {
        int cl = it*4 + cl_l;
        float v = x[(size_t)(b*NC + c0 + cl)*NS + sp0 + sp_l];
        tile[cl][sp_l] = (v - st.x) * st.y * gns[c0 + cl] + gnb[c0 + cl];
    }
    __syncthreads();
    int cc = tid & 63;
#pragma unroll
    for (int it = 0; it < 16; it++) {
        int sp = it*4 + (tid >> 6);
        float v = tile[cc][sp];
        size_t idx = (size_t)(b*NS + sp0 + sp)*NC + c0 + cc;
        __nv_bfloat16 h = __float2bfloat16(v);
        g_h_hi[idx] = h;
        g_h_lo[idx] = __float2bfloat16(v - __bfloat162float(h));
    }
}

// ============================================================
// mma.sync split-bf16 GEMM (as R4, MODE0 now emits bf16 hi/lo QKV)
// ============================================================
#define PITCH_B 144
#define STG_AL  (128*PITCH_B)
#define STG_B   (2*128*PITCH_B)
#define STG_BL  (3*128*PITCH_B)
#define STAGE_BYTES (4*128*PITCH_B)
#define GEMM_SMEM (2*STAGE_BYTES)

template<int MODE>
__global__ void __launch_bounds__(256, 1)
mm_gemm(const __nv_bfloat16* __restrict__ Ah, const __nv_bfloat16* __restrict__ Al,
        const __nv_bfloat16* __restrict__ Wh, const __nv_bfloat16* __restrict__ Wl,
        const float* __restrict__ bias,
        const float* __restrict__ addsrc, float* __restrict__ out,
        __nv_bfloat16* __restrict__ ohi, __nv_bfloat16* __restrict__ olo)
{
    extern __shared__ char smem[];
    uint32_t sb = smem_u32(smem);
    int tid = threadIdx.x, lane = tid & 31, wid = tid >> 5;
    int wm = wid >> 2, wn = wid & 3;
    int n0 = blockIdx.x << 7, m0 = blockIdx.y << 7;

    float D[4][4][4] = {};

    auto load_stage = [&](int s, int bb) {
        int k0 = s << 6;
        char* base = smem + bb*STAGE_BYTES;
#pragma unroll
        for (int it = 0; it < 8; it++) {
            int chunk = tid + it*256;
            int r = chunk >> 4, c = chunk & 15;
            size_t ga = (size_t)(m0 + r)*NC + k0 + c*4;
            size_t gb = (size_t)(n0 + r)*NC + k0 + c*4;
            uint32_t so = r*PITCH_B + c*8;
            *(uint2*)(base + so)          = *(const uint2*)(Ah + ga);
            *(uint2*)(base + STG_AL + so) = *(const uint2*)(Al + ga);
            *(uint2*)(base + STG_B  + so) = *(const uint2*)(Wh + gb);
            *(uint2*)(base + STG_BL + so) = *(const uint2*)(Wl + gb);
        }
    };

    uint32_t aOff = (uint32_t)(wm*64 + (lane & 15))*PITCH_B + (lane >> 4)*16;
    uint32_t bOff = (uint32_t)STG_B
                  + (uint32_t)(wn*32 + ((lane >> 4) & 1)*8 + (lane & 7))*PITCH_B
                  + ((lane >> 3) & 1)*16;

    load_stage(0, 0);
    __syncthreads();

    int buf = 0;
    for (int s = 0; s < 8; s++) {
        if (s < 7) load_stage(s + 1, buf ^ 1);
        uint32_t base = sb + buf*STAGE_BYTES;
#pragma unroll
        for (int ks = 0; ks < 4; ks++) {
            uint32_t ah[4][4], al[4][4], bh[2][4], bl[2][4];
#pragma unroll
            for (int i = 0; i < 4; i++) {
                uint32_t adr = base + aOff + i*(16*PITCH_B) + ks*32;
                ldsm4(ah[i][0], ah[i][1], ah[i][2], ah[i][3], adr);
                ldsm4(al[i][0], al[i][1], al[i][2], al[i][3], adr + STG_AL);
            }
#pragma unroll
            for (int j2 = 0; j2 < 2; j2++) {
                uint32_t adr = base + bOff + j2*(16*PITCH_B) + ks*32;
                ldsm4(bh[j2][0], bh[j2][1], bh[j2][2], bh[j2][3], adr);
                ldsm4(bl[j2][0], bl[j2][1], bl[j2][2], bl[j2][3], adr + STG_AL);
            }
#pragma unroll
            for (int i = 0; i < 4; i++)
#pragma unroll
                for (int j2 = 0; j2 < 2; j2++) {
                    mma16816(D[i][2*j2],   ah[i], &bh[j2][0]);
                    mma16816(D[i][2*j2],   al[i], &bh[j2][0]);
                    mma16816(D[i][2*j2],   ah[i], &bl[j2][0]);
                    mma16816(D[i][2*j2+1], ah[i], &bh[j2][2]);
                    mma16816(D[i][2*j2+1], al[i], &bh[j2][2]);
                    mma16816(D[i][2*j2+1], ah[i], &bl[j2][2]);
                }
        }
        __syncthreads();
        buf ^= 1;
    }

    int g = lane >> 2, tig = lane & 3;
#pragma unroll
    for (int i = 0; i < 4; i++) {
#pragma unroll
        for (int j = 0; j < 4; j++) {
            int Cn = n0 + wn*32 + j*8 + tig*2;
            float b0 = bias[Cn], b1 = bias[Cn+1];
#pragma unroll
            for (int hr = 0; hr < 2; hr++) {
                int R = m0 + wm*64 + i*16 + g + hr*8;
                float v0 = D[i][j][hr*2+0] + b0;
                float v1 = D[i][j][hr*2+1] + b1;
                if (MODE == 0) {
                    int b = R >> 10, sp = R & 1023;
                    int which = Cn >> 9, head = (Cn >> 6) & 7, d = Cn & 63;
                    if (which == 0) { v0 *= QSCALE; v1 *= QSCALE; }
                    __nv_bfloat16* dh = (which == 0) ? g_qh : (which == 1) ? g_kh : g_vh;
                    __nv_bfloat16* dl = (which == 0) ? g_ql : (which == 1) ? g_kl : g_vl;
                    size_t idx = (size_t)((b*NHD + head)*NS + sp)*HD + d;
                    __nv_bfloat16 h0 = __float2bfloat16(v0);
                    __nv_bfloat16 h1 = __float2bfloat16(v1);
                    __nv_bfloat162 hp; hp.x = h0; hp.y = h1;
                    *(__nv_bfloat162*)(dh + idx) = hp;
                    __nv_bfloat162 lp;
                    lp.x = __float2bfloat16(v0 - __bfloat162float(h0));
                    lp.y = __float2bfloat16(v1 - __bfloat162float(h1));
                    *(__nv_bfloat162*)(dl + idx) = lp;
                } else if (MODE == 1) {
                    size_t idx = (size_t)R*NC + Cn;
                    float2 s2 = *(const float2*)(addsrc + idx);
                    float r0 = s2.x + 0.1f*tanhf(v0);
                    float r1 = s2.y + 0.1f*tanhf(v1);
                    *(float2*)(out + idx) = make_float2(r0, r1);
                    __nv_bfloat16 h0 = __float2bfloat16(r0);
                    __nv_bfloat16 h1 = __float2bfloat16(r1);
                    __nv_bfloat162 hp; hp.x = h0; hp.y = h1;
                    *(__nv_bfloat162*)(ohi + idx) = hp;
                    __nv_bfloat162 lp;
                    lp.x = __float2bfloat16(r0 - __bfloat162float(h0));
                    lp.y = __float2bfloat16(r1 - __bfloat162float(h1));
                    *(__nv_bfloat162*)(olo + idx) = lp;
                } else {
                    int b = R >> 10, sp = R & 1023;
                    size_t basei = (size_t)(b*NC + Cn)*NS + sp;
                    out[basei     ] = addsrc[basei     ] + v0;
                    out[basei + NS] = addsrc[basei + NS] + v1;
                }
            }
        }
    }
}

// ============================================================
// FA2-style mma.sync split-bf16 attention.
// CTA = (b, h, 128-row q tile); 8 warps, each owns 16 q-rows x all kv.
// Softmax in base-2 domain (Q pre-scaled by 0.125*log2 e).
// ============================================================
#define APITCH 144
#define ATILE  (128*APITCH)          // 18432 bytes per matrix
#define ATT_SMEM (4*ATILE)           // Kh | Kl | Vh | Vl (Q staged in Kh/Kl first)

__global__ void __launch_bounds__(256, 1) attn_kernel() {
    extern __shared__ char smem[];
    uint32_t sb = smem_u32(smem);
    int tid = threadIdx.x, lane = tid & 31, w = tid >> 5;
    int qt = blockIdx.x, h = blockIdx.y, b = blockIdx.z;
    int g = lane >> 2, tig = lane & 3;
    size_t bh_off = (size_t)(b*NHD + h)*NS*HD;

    // ---- stage Q tile (hi/lo) and pull into A-frags ----
    {
        const __nv_bfloat16* Qh = g_qh + bh_off + (size_t)(qt<<7)*HD;
        const __nv_bfloat16* Ql = g_ql + bh_off + (size_t)(qt<<7)*HD;
#pragma unroll
        for (int it = 0; it < 4; it++) {
            int chunk = tid + it*256;          // 1024 chunks: row(128) x c(8)
            int r = chunk >> 3, c = chunk & 7;
            *(uint4*)(smem + r*APITCH + c*16)         = *(const uint4*)(Qh + (size_t)r*HD + c*8);
            *(uint4*)(smem + ATILE + r*APITCH + c*16) = *(const uint4*)(Ql + (size_t)r*HD + c*8);
        }
    }
    __syncthreads();
    uint32_t qh[4][4], ql[4][4];
    {
        uint32_t aOff = (uint32_t)(w*16 + (lane & 15))*APITCH + (lane >> 4)*16;
#pragma unroll
        for (int ks = 0; ks < 4; ks++) {
            uint32_t adr = sb + aOff + ks*32;
            ldsm4(qh[ks][0], qh[ks][1], qh[ks][2], qh[ks][3], adr);
            ldsm4(ql[ks][0], ql[ks][1], ql[ks][2], ql[ks][3], adr + ATILE);
        }
    }
    __syncthreads();

    float O[8][4] = {};
    float m0 = -1e30f, m1 = -1e30f, l0 = 0.f, l1 = 0.f;

    uint32_t kOff = (uint32_t)(((lane >> 4) & 1)*8 + (lane & 7))*APITCH
                  + ((lane >> 3) & 1)*16;
    uint32_t vOff = (uint32_t)(2*ATILE)
                  + (uint32_t)(((lane >> 3) & 1)*8 + (lane & 7))*APITCH
                  + ((lane >> 4) & 1)*16;

    for (int kt = 0; kt < 8; kt++) {
        size_t t0 = (size_t)(kt << 7);
        // ---- cooperative load K/V hi/lo tiles ----
        {
            const __nv_bfloat16* srcs[4] = {
                g_kh + bh_off + t0*HD, g_kl + bh_off + t0*HD,
                g_vh + bh_off + t0*HD, g_vl + bh_off + t0*HD };
#pragma unroll
            for (int mt = 0; mt < 4; mt++) {
                const __nv_bfloat16* s = srcs[mt];
                char* dst = smem + mt*ATILE;
#pragma unroll
                for (int it = 0; it < 4; it++) {
                    int chunk = tid + it*256;
                    int r = chunk >> 3, c = chunk & 7;
                    *(uint4*)(dst + r*APITCH + c*16) = *(const uint4*)(s + (size_t)r*HD + c*8);
                }
            }
        }
        __syncthreads();

        // ---- S = Q K^T (3-term split), frags S[16][4] ----
        float S[16][4];
#pragma unroll
        for (int i = 0; i < 16; i++) { S[i][0]=0.f; S[i][1]=0.f; S[i][2]=0.f; S[i][3]=0.f; }
#pragma unroll
        for (int ks = 0; ks < 4; ks++) {
#pragma unroll
            for (int nf = 0; nf < 8; nf++) {
                uint32_t kh4[4], kl4[4];
                uint32_t adr = sb + kOff + nf*(16*APITCH) + ks*32;
                ldsm4(kh4[0], kh4[1], kh4[2], kh4[3], adr);
                ldsm4(kl4[0], kl4[1], kl4[2], kl4[3], adr + ATILE);
                mma16816(S[2*nf],   qh[ks], &kh4[0]);
                mma16816(S[2*nf],   ql[ks], &kh4[0]);
                mma16816(S[2*nf],   qh[ks], &kl4[0]);
                mma16816(S[2*nf+1], qh[ks], &kh4[2]);
                mma16816(S[2*nf+1], ql[ks], &kh4[2]);
                mma16816(S[2*nf+1], qh[ks], &kl4[2]);
            }
        }

        // ---- softmax (base-2) ----
        float mx0 = -1e30f, mx1 = -1e30f;
#pragma unroll
        for (int i = 0; i < 16; i++) {
            mx0 = fmaxf(mx0, fmaxf(S[i][0], S[i][1]));
            mx1 = fmaxf(mx1, fmaxf(S[i][2], S[i][3]));
        }
        mx0 = fmaxf(mx0, __shfl_xor_sync(0xffffffff, mx0, 1));
        mx0 = fmaxf(mx0, __shfl_xor_sync(0xffffffff, mx0, 2));
        mx1 = fmaxf(mx1, __shfl_xor_sync(0xffffffff, mx1, 1));
        mx1 = fmaxf(mx1, __shfl_xor_sync(0xffffffff, mx1, 2));
        float mn0 = fmaxf(m0, mx0), mn1 = fmaxf(m1, mx1);
        float al0 = exp2f(m0 - mn0), al1 = exp2f(m1 - mn1);
        m0 = mn0; m1 = mn1;
        float sum0 = 0.f, sum1 = 0.f;
#pragma unroll
        for (int i = 0; i < 16; i++) {
            S[i][0] = exp2f(S[i][0] - mn0);
            S[i][1] = exp2f(S[i][1] - mn0);
            S[i][2] = exp2f(S[i][2] - mn1);
            S[i][3] = exp2f(S[i][3] - mn1);
            sum0 += S[i][0] + S[i][1];
            sum1 += S[i][2] + S[i][3];
        }
        sum0 += __shfl_xor_sync(0xffffffff, sum0, 1);
        sum0 += __shfl_xor_sync(0xffffffff, sum0, 2);
        sum1 += __shfl_xor_sync(0xffffffff, sum1, 1);
        sum1 += __shfl_xor_sync(0xffffffff, sum1, 2);
        l0 = l0*al0 + sum0;
        l1 = l1*al1 + sum1;
#pragma unroll
        for (int of = 0; of < 8; of++) {
            O[of][0]*=al0; O[of][1]*=al0; O[of][2]*=al1; O[of][3]*=al1;
        }

        // ---- O += P V (3-term split), P from S frags ----
#pragma unroll
        for (int t16 = 0; t16 < 8; t16++) {
            float* c0 = S[2*t16];
            float* c1 = S[2*t16+1];
            uint32_t pha[4], pla[4];
            {
                __nv_bfloat16 h00 = __float2bfloat16(c0[0]);
                __nv_bfloat16 h01 = __float2bfloat16(c0[1]);
                __nv_bfloat16 h02 = __float2bfloat16(c0[2]);
                __nv_bfloat16 h03 = __float2bfloat16(c0[3]);
                __nv_bfloat16 h10 = __float2bfloat16(c1[0]);
                __nv_bfloat16 h11 = __float2bfloat16(c1[1]);
                __nv_bfloat16 h12 = __float2bfloat16(c1[2]);
                __nv_bfloat16 h13 = __float2bfloat16(c1[3]);
                __nv_bfloat162 t;
                t.x=h00; t.y=h01; pha[0]=*(uint32_t*)&t;
                t.x=h02; t.y=h03; pha[1]=*(uint32_t*)&t;
                t.x=h10; t.y=h11; pha[2]=*(uint32_t*)&t;
                t.x=h12; t.y=h13; pha[3]=*(uint32_t*)&t;
                pla[0] = pack_bf2(c0[0]-__bfloat162float(h00), c0[1]-__bfloat162float(h01));
                pla[1] = pack_bf2(c0[2]-__bfloat162float(h02), c0[3]-__bfloat162float(h03));
                pla[2] = pack_bf2(c1[0]-__bfloat162float(h10), c1[1]-__bfloat162float(h11));
                pla[3] = pack_bf2(c1[2]-__bfloat162float(h12), c1[3]-__bfloat162float(h13));
            }
#pragma unroll
            for (int db = 0; db < 4; db++) {
                uint32_t vh4[4], vl4[4];
                uint32_t adr = sb + vOff + t16*(16*APITCH) + db*32;
                ldsm4t(vh4[0], vh4[1], vh4[2], vh4[3], adr);
                ldsm4t(vl4[0], vl4[1], vl4[2], vl4[3], adr + ATILE);
                mma16816(O[2*db],   pha, &vh4[0]);
                mma16816(O[2*db],   pla, &vh4[0]);
                mma16816(O[2*db],   pha, &vl4[0]);
                mma16816(O[2*db+1], pha, &vh4[2]);
                mma16816(O[2*db+1], pla, &vh4[2]);
                mma16816(O[2*db+1], pha, &vl4[2]);
            }
        }
        __syncthreads();
    }

    // ---- epilogue: normalize, write g_hf fp32 + bf16 hi/lo ----
    float inv0 = 1.f / l0, inv1 = 1.f / l1;
    int r0g = (qt<<7) + w*16 + g;
#pragma unroll
    for (int of = 0; of < 8; of++) {
        int d0 = of*8 + tig*2;
        float a0 = O[of][0]*inv0, a1 = O[of][1]*inv0;
        float a2 = O[of][2]*inv1, a3 = O[of][3]*inv1;
        size_t i0 = (size_t)(b*NS + r0g)*NC + h*HD + d0;
        size_t i1 = (size_t)(b*NS + r0g + 8)*NC + h*HD + d0;
        *(float2*)(g_hf + i0) = make_float2(a0, a1);
        *(float2*)(g_hf + i1) = make_float2(a2, a3);
        __nv_bfloat16 h0 = __float2bfloat16(a0), h1 = __float2bfloat16(a1);
        __nv_bfloat16 h2 = __float2bfloat16(a2), h3 = __float2bfloat16(a3);
        __nv_bfloat162 p;
        p.x=h0; p.y=h1; *(__nv_bfloat162*)(g_hf_hi + i0) = p;
        p.x=h2; p.y=h3; *(__nv_bfloat162*)(g_hf_hi + i1) = p;
        p.x=__float2bfloat16(a0-__bfloat162float(h0));
        p.y=__float2bfloat16(a1-__bfloat162float(h1));
        *(__nv_bfloat162*)(g_hf_lo + i0) = p;
        p.x=__float2bfloat16(a2-__bfloat162float(h2));
        p.y=__float2bfloat16(a3-__bfloat162float(h3));
        *(__nv_bfloat162*)(g_hf_lo + i1) = p;
    }
}

// ============================================================
// launch
// ============================================================
extern "C" void kernel_launch(void* const* d_in, const int* in_sizes, int n_in,
                              void* d_out, int out_size) {
    const float* x      = (const float*)d_in[0];
    const float* gns    = (const float*)d_in[1];
    const float* gnb    = (const float*)d_in[2];
    const float* qkv_w  = (const float*)d_in[3];
    const float* qkv_b  = (const float*)d_in[4];
    const float* proj_w = (const float*)d_in[5];
    const float* proj_b = (const float*)d_in[6];
    const float* inl_w  = (const float*)d_in[7];
    const float* inl_b  = (const float*)d_in[8];
    float* out = (float*)d_out;

    __nv_bfloat16 *hh, *hl, *wqh, *wql, *wih, *wil, *wph, *wpl;
    __nv_bfloat16 *hfh, *hfl, *hf2h, *hf2l;
    float *hf, *hf2;
    cudaGetSymbolAddress((void**)&hh,   g_h_hi);
    cudaGetSymbolAddress((void**)&hl,   g_h_lo);
    cudaGetSymbolAddress((void**)&wqh,  g_wq_hi);
    cudaGetSymbolAddress((void**)&wql,  g_wq_lo);
    cudaGetSymbolAddress((void**)&wih,  g_wi_hi);
    cudaGetSymbolAddress((void**)&wil,  g_wi_lo);
    cudaGetSymbolAddress((void**)&wph,  g_wp_hi);
    cudaGetSymbolAddress((void**)&wpl,  g_wp_lo);
    cudaGetSymbolAddress((void**)&hf,   g_hf);
    cudaGetSymbolAddress((void**)&hf2,  g_hf2);
    cudaGetSymbolAddress((void**)&hfh,  g_hf_hi);
    cudaGetSymbolAddress((void**)&hfl,  g_hf_lo);
    cudaGetSymbolAddress((void**)&hf2h, g_hf2_hi);
    cudaGetSymbolAddress((void**)&hf2l, g_hf2_lo);

    cudaFuncSetAttribute((const void*)attn_kernel,
                         cudaFuncAttributeMaxDynamicSharedMemorySize, ATT_SMEM);
    cudaFuncSetAttribute((const void*)mm_gemm<0>,
                         cudaFuncAttributeMaxDynamicSharedMemorySize, GEMM_SMEM);
    cudaFuncSetAttribute((const void*)mm_gemm<1>,
                         cudaFuncAttributeMaxDynamicSharedMemorySize, GEMM_SMEM);
    cudaFuncSetAttribute((const void*)mm_gemm<2>,
                         cudaFuncAttributeMaxDynamicSharedMemorySize, GEMM_SMEM);

    cvt_kernel<<<(3*NC*NC + 255)/256, 256>>>(qkv_w,  wqh, wql, 3*NC*NC);
    cvt_kernel<<<(NC*NC   + 255)/256, 256>>>(inl_w,  wih, wil, NC*NC);
    cvt_kernel<<<(NC*NC   + 255)/256, 256>>>(proj_w, wph, wpl, NC*NC);
    gn_stats1<<<512, 256>>>(x);
    gn_stats2<<<1, 64>>>();
    gn_apply<<<dim3(16, 8, 8), 256>>>(x, gns, gnb);

    mm_gemm<0><<<dim3(12, 64), 256, GEMM_SMEM>>>(hh, hl, wqh, wql, qkv_b,
                                                 nullptr, nullptr, nullptr, nullptr);
    attn_kernel<<<dim3(8, 8, 8), 256, ATT_SMEM>>>();
    mm_gemm<1><<<dim3(4, 64), 256, GEMM_SMEM>>>(hfh, hfl, wih, wil, inl_b,
                                                hf, hf2, hf2h, hf2l);
    mm_gemm<1><<<dim3(4, 64), 256, GEMM_SMEM>>>(hf2h, hf2l, wih, wil, inl_b,
                                                hf2, hf, hfh, hfl);
    mm_gemm<1><<<dim3(4, 64), 256, GEMM_SMEM>>>(hfh, hfl, wih, wil, inl_b,
                                                hf, hf2, hf2h, hf2l);
    mm_gemm<2><<<dim3(4, 64), 256, GEMM_SMEM>>>(hf2h, hf2l, wph, wpl, proj_b,
                                                x, out, nullptr, nullptr);
}

// round 6
// speedup vs baseline: 2.9575x; 1.0592x over previous
#include <cuda_runtime.h>
#include <cuda_bf16.h>
#include <math.h>
#include <cstdint>

#define NB 8
#define NC 512
#define NS 1024
#define NHD 8
#define HD 64
#define QSCALE 0.180336540f   // 0.125 * log2(e)

// ---- scratch (static __device__, no allocs) ----
__device__ __nv_bfloat16 g_h_hi [NB*NS*NC];
__device__ __nv_bfloat16 g_h_lo [NB*NS*NC];
__device__ __nv_bfloat16 g_qh[NB*NHD*NS*HD], g_ql[NB*NHD*NS*HD];
__device__ __nv_bfloat16 g_kh[NB*NHD*NS*HD], g_kl[NB*NHD*NS*HD];
__device__ __nv_bfloat16 g_vh[NB*NHD*NS*HD], g_vl[NB*NHD*NS*HD];
__device__ __nv_bfloat16 g_hf_hi [NB*NS*NC];
__device__ __nv_bfloat16 g_hf_lo [NB*NS*NC];
__device__ __nv_bfloat16 g_hf2_hi[NB*NS*NC];
__device__ __nv_bfloat16 g_hf2_lo[NB*NS*NC];
__device__ __nv_bfloat16 g_wq_hi[3*NC*NC], g_wq_lo[3*NC*NC];
__device__ __nv_bfloat16 g_wi_hi[NC*NC],   g_wi_lo[NC*NC];
__device__ __nv_bfloat16 g_wp_hi[NC*NC],   g_wp_lo[NC*NC];
__device__ float2 g_part[512];
__device__ float2 g_stat[64];

__device__ __forceinline__ uint32_t smem_u32(const void* p) {
    uint32_t a;
    asm("{ .reg .u64 t; cvta.to.shared.u64 t, %1; cvt.u32.u64 %0, t; }" : "=r"(a) : "l"(p));
    return a;
}
__device__ __forceinline__ void cp16(uint32_t dst, const void* src) {
    asm volatile("cp.async.cg.shared.global [%0], [%1], 16;" :: "r"(dst), "l"(src));
}
#define CP_COMMIT() asm volatile("cp.async.commit_group;" ::: "memory")
#define CP_WAIT1()  asm volatile("cp.async.wait_group 1;" ::: "memory")
#define CP_WAIT0()  asm volatile("cp.async.wait_group 0;" ::: "memory")
__device__ __forceinline__ void ldsm4(uint32_t& r0, uint32_t& r1, uint32_t& r2,
                                      uint32_t& r3, uint32_t addr) {
    asm volatile("ldmatrix.sync.aligned.m8n8.x4.shared.b16 {%0,%1,%2,%3}, [%4];"
                 : "=r"(r0), "=r"(r1), "=r"(r2), "=r"(r3) : "r"(addr));
}
__device__ __forceinline__ void ldsm4t(uint32_t& r0, uint32_t& r1, uint32_t& r2,
                                       uint32_t& r3, uint32_t addr) {
    asm volatile("ldmatrix.sync.aligned.m8n8.x4.trans.shared.b16 {%0,%1,%2,%3}, [%4];"
                 : "=r"(r0), "=r"(r1), "=r"(r2), "=r"(r3) : "r"(addr));
}
__device__ __forceinline__ void mma16816(float* d, const uint32_t* a, const uint32_t* b) {
    asm volatile("mma.sync.aligned.m16n8k16.row.col.f32.bf16.bf16.f32 "
        "{%0,%1,%2,%3},{%4,%5,%6,%7},{%8,%9},{%0,%1,%2,%3};"
        : "+f"(d[0]), "+f"(d[1]), "+f"(d[2]), "+f"(d[3])
        : "r"(a[0]), "r"(a[1]), "r"(a[2]), "r"(a[3]), "r"(b[0]), "r"(b[1]));
}
__device__ __forceinline__ uint32_t pack_bf2(float a, float b) {
    __nv_bfloat162 t; t.x = __float2bfloat16(a); t.y = __float2bfloat16(b);
    return *(uint32_t*)&t;
}

// ============================================================
// weight fp32 -> bf16 hi/lo
// ============================================================
__global__ void cvt_kernel(const float* __restrict__ src,
                           __nv_bfloat16* __restrict__ hi,
                           __nv_bfloat16* __restrict__ lo, int n) {
    int i = blockIdx.x * 256 + threadIdx.x;
    if (i < n) {
        float v = src[i];
        __nv_bfloat16 h = __float2bfloat16(v);
        hi[i] = h;
        lo[i] = __float2bfloat16(v - __bfloat162float(h));
    }
}

// ============================================================
// GroupNorm, 3-stage
// ============================================================
__global__ void gn_stats1(const float* __restrict__ x) {
    int bg = blockIdx.x >> 3, chunk = blockIdx.x & 7;
    const float4* xp = (const float4*)(x + (size_t)bg*65536 + chunk*8192);
    int tid = threadIdx.x;
    float s1 = 0.f, s2 = 0.f;
#pragma unroll
    for (int it = 0; it < 8; it++) {
        float4 v = xp[tid + it*256];
        s1 += v.x + v.y + v.z + v.w;
        s2 += v.x*v.x + v.y*v.y + v.z*v.z + v.w*v.w;
    }
    __shared__ float r1[256], r2[256];
    r1[tid] = s1; r2[tid] = s2;
    __syncthreads();
    for (int o = 128; o > 0; o >>= 1) {
        if (tid < o) { r1[tid] += r1[tid+o]; r2[tid] += r2[tid+o]; }
        __syncthreads();
    }
    if (tid == 0) g_part[blockIdx.x] = make_float2(r1[0], r2[0]);
}
__global__ void gn_stats2() {
    int g = threadIdx.x;
    float s1 = 0.f, s2 = 0.f;
#pragma unroll
    for (int i = 0; i < 8; i++) {
        float2 p = g_part[g*8 + i];
        s1 += p.x; s2 += p.y;
    }
    float mean = s1 * (1.f/65536.f);
    float var  = s2 * (1.f/65536.f) - mean*mean;
    g_stat[g] = make_float2(mean, rsqrtf(var + 1e-5f));
}
__global__ void gn_apply(const float* __restrict__ x,
                         const float* __restrict__ gns,
                         const float* __restrict__ gnb) {
    __shared__ float tile[64][65];
    int sp0 = blockIdx.x << 6, c0 = blockIdx.y << 6, b = blockIdx.z;
    int tid = threadIdx.x;
    float2 st = g_stat[b*8 + blockIdx.y];
    int cl_l = tid >> 6, sp_l = tid & 63;
#pragma unroll
    for (int it = 0; it < 16; it++) {
        int cl = it*4 + cl_l;
        float v = x[(size_t)(b*NC + c0 + cl)*NS + sp0 + sp_l];
        tile[cl][sp_l] = (v - st.x) * st.y * gns[c0 + cl] + gnb[c0 + cl];
    }
    __syncthreads();
    int cc = tid & 63;
#pragma unroll
    for (int it = 0; it < 16; it++) {
        int sp = it*4 + (tid >> 6);
        float v = tile[cc][sp];
        size_t idx = (size_t)(b*NS + sp0 + sp)*NC + c0 + cc;
        __nv_bfloat16 h = __float2bfloat16(v);
        g_h_hi[idx] = h;
        g_h_lo[idx] = __float2bfloat16(v - __bfloat162float(h));
    }
}

// ============================================================
// mma.sync split-bf16 GEMM, cp.async double-buffered.
// MODE 0: qkv scatter (bf16 hi/lo, Q pre-scaled)
// MODE 1: INL tanh step (residual reconstructed from Ah+Al, out hi/lo)
// MODE 2: proj + residual (addsrc = x fp32, out fp32)
// ============================================================
#define PITCH_B 144
#define STG_AL  (128*PITCH_B)
#define STG_B   (2*128*PITCH_B)
#define STG_BL  (3*128*PITCH_B)
#define STAGE_BYTES (4*128*PITCH_B)
#define GEMM_SMEM (2*STAGE_BYTES)

template<int MODE>
__global__ void __launch_bounds__(256, 1)
mm_gemm(const __nv_bfloat16* __restrict__ Ah, const __nv_bfloat16* __restrict__ Al,
        const __nv_bfloat16* __restrict__ Wh, const __nv_bfloat16* __restrict__ Wl,
        const float* __restrict__ bias,
        const float* __restrict__ addsrc, float* __restrict__ out,
        __nv_bfloat16* __restrict__ ohi, __nv_bfloat16* __restrict__ olo)
{
    extern __shared__ char smem[];
    uint32_t sb = smem_u32(smem);
    int tid = threadIdx.x, lane = tid & 31, wid = tid >> 5;
    int wm = wid >> 2, wn = wid & 3;
    int n0 = blockIdx.x << 7, m0 = blockIdx.y << 7;

    float D[4][4][4] = {};

    auto load_stage = [&](int s, int bb) {
        int k0 = s << 6;
        uint32_t base = sb + bb*STAGE_BYTES;
#pragma unroll
        for (int it = 0; it < 4; it++) {
            int chunk = tid + it*256;          // 1024 chunks of 16B per matrix
            int r = chunk >> 3, c = chunk & 7;
            size_t ga = (size_t)(m0 + r)*NC + k0 + c*8;
            size_t gb = (size_t)(n0 + r)*NC + k0 + c*8;
            uint32_t so = r*PITCH_B + c*16;
            cp16(base + so,          Ah + ga);
            cp16(base + STG_AL + so, Al + ga);
            cp16(base + STG_B  + so, Wh + gb);
            cp16(base + STG_BL + so, Wl + gb);
        }
        CP_COMMIT();
    };

    uint32_t aOff = (uint32_t)(wm*64 + (lane & 15))*PITCH_B + (lane >> 4)*16;
    uint32_t bOff = (uint32_t)STG_B
                  + (uint32_t)(wn*32 + ((lane >> 4) & 1)*8 + (lane & 7))*PITCH_B
                  + ((lane >> 3) & 1)*16;

    load_stage(0, 0);

    int buf = 0;
    for (int s = 0; s < 8; s++) {
        if (s < 7) { load_stage(s + 1, buf ^ 1); CP_WAIT1(); }
        else       { CP_WAIT0(); }
        __syncthreads();
        uint32_t base = sb + buf*STAGE_BYTES;
#pragma unroll
        for (int ks = 0; ks < 4; ks++) {
            uint32_t ah[4][4], al[4][4], bh[2][4], bl[2][4];
#pragma unroll
            for (int i = 0; i < 4; i++) {
                uint32_t adr = base + aOff + i*(16*PITCH_B) + ks*32;
                ldsm4(ah[i][0], ah[i][1], ah[i][2], ah[i][3], adr);
                ldsm4(al[i][0], al[i][1], al[i][2], al[i][3], adr + STG_AL);
            }
#pragma unroll
            for (int j2 = 0; j2 < 2; j2++) {
                uint32_t adr = base + bOff + j2*(16*PITCH_B) + ks*32;
                ldsm4(bh[j2][0], bh[j2][1], bh[j2][2], bh[j2][3], adr);
                ldsm4(bl[j2][0], bl[j2][1], bl[j2][2], bl[j2][3], adr + STG_AL);
            }
#pragma unroll
            for (int i = 0; i < 4; i++)
#pragma unroll
                for (int j2 = 0; j2 < 2; j2++) {
                    mma16816(D[i][2*j2],   ah[i], &bh[j2][0]);
                    mma16816(D[i][2*j2],   al[i], &bh[j2][0]);
                    mma16816(D[i][2*j2],   ah[i], &bl[j2][0]);
                    mma16816(D[i][2*j2+1], ah[i], &bh[j2][2]);
                    mma16816(D[i][2*j2+1], al[i], &bh[j2][2]);
                    mma16816(D[i][2*j2+1], ah[i], &bl[j2][2]);
                }
        }
        __syncthreads();
        buf ^= 1;
    }

    int g = lane >> 2, tig = lane & 3;
#pragma unroll
    for (int i = 0; i < 4; i++) {
#pragma unroll
        for (int j = 0; j < 4; j++) {
            int Cn = n0 + wn*32 + j*8 + tig*2;
            float b0 = bias[Cn], b1 = bias[Cn+1];
#pragma unroll
            for (int hr = 0; hr < 2; hr++) {
                int R = m0 + wm*64 + i*16 + g + hr*8;
                float v0 = D[i][j][hr*2+0] + b0;
                float v1 = D[i][j][hr*2+1] + b1;
                if (MODE == 0) {
                    int b = R >> 10, sp = R & 1023;
                    int which = Cn >> 9, head = (Cn >> 6) & 7, d = Cn & 63;
                    if (which == 0) { v0 *= QSCALE; v1 *= QSCALE; }
                    __nv_bfloat16* dh = (which == 0) ? g_qh : (which == 1) ? g_kh : g_vh;
                    __nv_bfloat16* dl = (which == 0) ? g_ql : (which == 1) ? g_kl : g_vl;
                    size_t idx = (size_t)((b*NHD + head)*NS + sp)*HD + d;
                    __nv_bfloat16 h0 = __float2bfloat16(v0);
                    __nv_bfloat16 h1 = __float2bfloat16(v1);
                    __nv_bfloat162 hp; hp.x = h0; hp.y = h1;
                    *(__nv_bfloat162*)(dh + idx) = hp;
                    __nv_bfloat162 lp;
                    lp.x = __float2bfloat16(v0 - __bfloat162float(h0));
                    lp.y = __float2bfloat16(v1 - __bfloat162float(h1));
                    *(__nv_bfloat162*)(dl + idx) = lp;
                } else if (MODE == 1) {
                    size_t idx = (size_t)R*NC + Cn;
                    __nv_bfloat162 sh = *(const __nv_bfloat162*)(Ah + idx);
                    __nv_bfloat162 sl = *(const __nv_bfloat162*)(Al + idx);
                    float a0 = __bfloat162float(sh.x) + __bfloat162float(sl.x);
                    float a1 = __bfloat162float(sh.y) + __bfloat162float(sl.y);
                    float r0 = a0 + 0.1f*tanhf(v0);
                    float r1 = a1 + 0.1f*tanhf(v1);
                    __nv_bfloat16 h0 = __float2bfloat16(r0);
                    __nv_bfloat16 h1 = __float2bfloat16(r1);
                    __nv_bfloat162 hp; hp.x = h0; hp.y = h1;
                    *(__nv_bfloat162*)(ohi + idx) = hp;
                    __nv_bfloat162 lp;
                    lp.x = __float2bfloat16(r0 - __bfloat162float(h0));
                    lp.y = __float2bfloat16(r1 - __bfloat162float(h1));
                    *(__nv_bfloat162*)(olo + idx) = lp;
                } else {
                    int b = R >> 10, sp = R & 1023;
                    size_t basei = (size_t)(b*NC + Cn)*NS + sp;
                    out[basei     ] = addsrc[basei     ] + v0;
                    out[basei + NS] = addsrc[basei + NS] + v1;
                }
            }
        }
    }
}

// ============================================================
// FA2-style mma.sync split-bf16 attention, cp.async dbl-buffered K/V,
// Q frags loaded straight from gmem.
// ============================================================
#define APITCH 144
#define ATILE  (128*APITCH)          // 18432 bytes
#define ABUF   (4*ATILE)             // Kh | Kl | Vh | Vl
#define ATT_SMEM (2*ABUF)            // 147456

__global__ void __launch_bounds__(256, 1) attn_kernel() {
    extern __shared__ char smem[];
    uint32_t sb = smem_u32(smem);
    int tid = threadIdx.x, lane = tid & 31, w = tid >> 5;
    int qt = blockIdx.x, h = blockIdx.y, b = blockIdx.z;
    int g = lane >> 2, tig = lane & 3;
    size_t bh_off = (size_t)(b*NHD + h)*NS*HD;

    const __nv_bfloat16* Kh = g_kh + bh_off;
    const __nv_bfloat16* Kl = g_kl + bh_off;
    const __nv_bfloat16* Vh = g_vh + bh_off;
    const __nv_bfloat16* Vl = g_vl + bh_off;

    auto load_kv = [&](int kt, int bb) {
        size_t t0HD = (size_t)(kt << 7) * HD;
        uint32_t base = sb + bb*ABUF;
#pragma unroll
        for (int it = 0; it < 4; it++) {
            int chunk = tid + it*256;
            int r = chunk >> 3, c = chunk & 7;
            uint32_t so = r*APITCH + c*16;
            size_t goff = t0HD + (size_t)r*HD + c*8;
            cp16(base + so,           Kh + goff);
            cp16(base + ATILE + so,   Kl + goff);
            cp16(base + 2*ATILE + so, Vh + goff);
            cp16(base + 3*ATILE + so, Vl + goff);
        }
        CP_COMMIT();
    };

    load_kv(0, 0);

    // ---- Q frags direct from gmem ----
    uint32_t qh[4][4], ql[4][4];
    {
        const __nv_bfloat16* Qh = g_qh + bh_off + (size_t)(qt<<7)*HD;
        const __nv_bfloat16* Ql = g_ql + bh_off + (size_t)(qt<<7)*HD;
        int r0 = w*16 + g;
#pragma unroll
        for (int ks = 0; ks < 4; ks++) {
            int c0 = ks*16 + tig*2;
            qh[ks][0] = *(const uint32_t*)(Qh + (size_t)r0*HD + c0);
            qh[ks][1] = *(const uint32_t*)(Qh + (size_t)(r0+8)*HD + c0);
            qh[ks][2] = *(const uint32_t*)(Qh + (size_t)r0*HD + c0 + 8);
            qh[ks][3] = *(const uint32_t*)(Qh + (size_t)(r0+8)*HD + c0 + 8);
            ql[ks][0] = *(const uint32_t*)(Ql + (size_t)r0*HD + c0);
            ql[ks][1] = *(const uint32_t*)(Ql + (size_t)(r0+8)*HD + c0);
            ql[ks][2] = *(const uint32_t*)(Ql + (size_t)r0*HD + c0 + 8);
            ql[ks][3] = *(const uint32_t*)(Ql + (size_t)(r0+8)*HD + c0 + 8);
        }
    }

    float O[8][4] = {};
    float m0 = -1e30f, m1 = -1e30f, l0 = 0.f, l1 = 0.f;

    uint32_t kOff = (uint32_t)(((lane >> 4) & 1)*8 + (lane & 7))*APITCH
                  + ((lane >> 3) & 1)*16;
    uint32_t vOff = (uint32_t)(2*ATILE)
                  + (uint32_t)(((lane >> 3) & 1)*8 + (lane & 7))*APITCH
                  + ((lane >> 4) & 1)*16;

    int buf = 0;
    for (int kt = 0; kt < 8; kt++) {
        if (kt < 7) { load_kv(kt + 1, buf ^ 1); CP_WAIT1(); }
        else        { CP_WAIT0(); }
        __syncthreads();
        uint32_t base = sb + buf*ABUF;

        // ---- S = Q K^T (3-term split) ----
        float S[16][4];
#pragma unroll
        for (int i = 0; i < 16; i++) { S[i][0]=0.f; S[i][1]=0.f; S[i][2]=0.f; S[i][3]=0.f; }
#pragma unroll
        for (int ks = 0; ks < 4; ks++) {
#pragma unroll
            for (int nf = 0; nf < 8; nf++) {
                uint32_t kh4[4], kl4[4];
                uint32_t adr = base + kOff + nf*(16*APITCH) + ks*32;
                ldsm4(kh4[0], kh4[1], kh4[2], kh4[3], adr);
                ldsm4(kl4[0], kl4[1], kl4[2], kl4[3], adr + ATILE);
                mma16816(S[2*nf],   qh[ks], &kh4[0]);
                mma16816(S[2*nf],   ql[ks], &kh4[0]);
                mma16816(S[2*nf],   qh[ks], &kl4[0]);
                mma16816(S[2*nf+1], qh[ks], &kh4[2]);
                mma16816(S[2*nf+1], ql[ks], &kh4[2]);
                mma16816(S[2*nf+1], qh[ks], &kl4[2]);
            }
        }

        // ---- softmax (base-2) ----
        float mx0 = -1e30f, mx1 = -1e30f;
#pragma unroll
        for (int i = 0; i < 16; i++) {
            mx0 = fmaxf(mx0, fmaxf(S[i][0], S[i][1]));
            mx1 = fmaxf(mx1, fmaxf(S[i][2], S[i][3]));
        }
        mx0 = fmaxf(mx0, __shfl_xor_sync(0xffffffff, mx0, 1));
        mx0 = fmaxf(mx0, __shfl_xor_sync(0xffffffff, mx0, 2));
        mx1 = fmaxf(mx1, __shfl_xor_sync(0xffffffff, mx1, 1));
        mx1 = fmaxf(mx1, __shfl_xor_sync(0xffffffff, mx1, 2));
        float mn0 = fmaxf(m0, mx0), mn1 = fmaxf(m1, mx1);
        float al0 = exp2f(m0 - mn0), al1 = exp2f(m1 - mn1);
        m0 = mn0; m1 = mn1;
        float sum0 = 0.f, sum1 = 0.f;
#pragma unroll
        for (int i = 0; i < 16; i++) {
            S[i][0] = exp2f(S[i][0] - mn0);
            S[i][1] = exp2f(S[i][1] - mn0);
            S[i][2] = exp2f(S[i][2] - mn1);
            S[i][3] = exp2f(S[i][3] - mn1);
            sum0 += S[i][0] + S[i][1];
            sum1 += S[i][2] + S[i][3];
        }
        sum0 += __shfl_xor_sync(0xffffffff, sum0, 1);
        sum0 += __shfl_xor_sync(0xffffffff, sum0, 2);
        sum1 += __shfl_xor_sync(0xffffffff, sum1, 1);
        sum1 += __shfl_xor_sync(0xffffffff, sum1, 2);
        l0 = l0*al0 + sum0;
        l1 = l1*al1 + sum1;
#pragma unroll
        for (int of = 0; of < 8; of++) {
            O[of][0]*=al0; O[of][1]*=al0; O[of][2]*=al1; O[of][3]*=al1;
        }

        // ---- O += P V (3-term split) ----
#pragma unroll
        for (int t16 = 0; t16 < 8; t16++) {
            float* c0 = S[2*t16];
            float* c1 = S[2*t16+1];
            uint32_t pha[4], pla[4];
            {
                __nv_bfloat16 h00 = __float2bfloat16(c0[0]);
                __nv_bfloat16 h01 = __float2bfloat16(c0[1]);
                __nv_bfloat16 h02 = __float2bfloat16(c0[2]);
                __nv_bfloat16 h03 = __float2bfloat16(c0[3]);
                __nv_bfloat16 h10 = __float2bfloat16(c1[0]);
                __nv_bfloat16 h11 = __float2bfloat16(c1[1]);
                __nv_bfloat16 h12 = __float2bfloat16(c1[2]);
                __nv_bfloat16 h13 = __float2bfloat16(c1[3]);
                __nv_bfloat162 t;
                t.x=h00; t.y=h01; pha[0]=*(uint32_t*)&t;
                t.x=h02; t.y=h03; pha[1]=*(uint32_t*)&t;
                t.x=h10; t.y=h11; pha[2]=*(uint32_t*)&t;
                t.x=h12; t.y=h13; pha[3]=*(uint32_t*)&t;
                pla[0] = pack_bf2(c0[0]-__bfloat162float(h00), c0[1]-__bfloat162float(h01));
                pla[1] = pack_bf2(c0[2]-__bfloat162float(h02), c0[3]-__bfloat162float(h03));
                pla[2] = pack_bf2(c1[0]-__bfloat162float(h10), c1[1]-__bfloat162float(h11));
                pla[3] = pack_bf2(c1[2]-__bfloat162float(h12), c1[3]-__bfloat162float(h13));
            }
#pragma unroll
            for (int db = 0; db < 4; db++) {
                uint32_t vh4[4], vl4[4];
                uint32_t adr = base + vOff + t16*(16*APITCH) + db*32;
                ldsm4t(vh4[0], vh4[1], vh4[2], vh4[3], adr);
                ldsm4t(vl4[0], vl4[1], vl4[2], vl4[3], adr + ATILE);
                mma16816(O[2*db],   pha, &vh4[0]);
                mma16816(O[2*db],   pla, &vh4[0]);
                mma16816(O[2*db],   pha, &vl4[0]);
                mma16816(O[2*db+1], pha, &vh4[2]);
                mma16816(O[2*db+1], pla, &vh4[2]);
                mma16816(O[2*db+1], pha, &vl4[2]);
            }
        }
        __syncthreads();
        buf ^= 1;
    }

    // ---- epilogue: normalize, write bf16 hi/lo only ----
    float inv0 = 1.f / l0, inv1 = 1.f / l1;
    int r0g = (qt<<7) + w*16 + g;
#pragma unroll
    for (int of = 0; of < 8; of++) {
        int d0 = of*8 + tig*2;
        float a0 = O[of][0]*inv0, a1 = O[of][1]*inv0;
        float a2 = O[of][2]*inv1, a3 = O[of][3]*inv1;
        size_t i0 = (size_t)(b*NS + r0g)*NC + h*HD + d0;
        size_t i1 = (size_t)(b*NS + r0g + 8)*NC + h*HD + d0;
        __nv_bfloat16 h0 = __float2bfloat16(a0), h1 = __float2bfloat16(a1);
        __nv_bfloat16 h2 = __float2bfloat16(a2), h3 = __float2bfloat16(a3);
        __nv_bfloat162 p;
        p.x=h0; p.y=h1; *(__nv_bfloat162*)(g_hf_hi + i0) = p;
        p.x=h2; p.y=h3; *(__nv_bfloat162*)(g_hf_hi + i1) = p;
        p.x=__float2bfloat16(a0-__bfloat162float(h0));
        p.y=__float2bfloat16(a1-__bfloat162float(h1));
        *(__nv_bfloat162*)(g_hf_lo + i0) = p;
        p.x=__float2bfloat16(a2-__bfloat162float(h2));
        p.y=__float2bfloat16(a3-__bfloat162float(h3));
        *(__nv_bfloat162*)(g_hf_lo + i1) = p;
    }
}

// ============================================================
// launch
// ============================================================
extern "C" void kernel_launch(void* const* d_in, const int* in_sizes, int n_in,
                              void* d_out, int out_size) {
    const float* x      = (const float*)d_in[0];
    const float* gns    = (const float*)d_in[1];
    const float* gnb    = (const float*)d_in[2];
    const float* qkv_w  = (const float*)d_in[3];
    const float* qkv_b  = (const float*)d_in[4];
    const float* proj_w = (const float*)d_in[5];
    const float* proj_b = (const float*)d_in[6];
    const float* inl_w  = (const float*)d_in[7];
    const float* inl_b  = (const float*)d_in[8];
    float* out = (float*)d_out;

    __nv_bfloat16 *hh, *hl, *wqh, *wql, *wih, *wil, *wph, *wpl;
    __nv_bfloat16 *hfh, *hfl, *hf2h, *hf2l;
    cudaGetSymbolAddress((void**)&hh,   g_h_hi);
    cudaGetSymbolAddress((void**)&hl,   g_h_lo);
    cudaGetSymbolAddress((void**)&wqh,  g_wq_hi);
    cudaGetSymbolAddress((void**)&wql,  g_wq_lo);
    cudaGetSymbolAddress((void**)&wih,  g_wi_hi);
    cudaGetSymbolAddress((void**)&wil,  g_wi_lo);
    cudaGetSymbolAddress((void**)&wph,  g_wp_hi);
    cudaGetSymbolAddress((void**)&wpl,  g_wp_lo);
    cudaGetSymbolAddress((void**)&hfh,  g_hf_hi);
    cudaGetSymbolAddress((void**)&hfl,  g_hf_lo);
    cudaGetSymbolAddress((void**)&hf2h, g_hf2_hi);
    cudaGetSymbolAddress((void**)&hf2l, g_hf2_lo);

    cudaFuncSetAttribute((const void*)attn_kernel,
                         cudaFuncAttributeMaxDynamicSharedMemorySize, ATT_SMEM);
    cudaFuncSetAttribute((const void*)mm_gemm<0>,
                         cudaFuncAttributeMaxDynamicSharedMemorySize, GEMM_SMEM);
    cudaFuncSetAttribute((const void*)mm_gemm<1>,
                         cudaFuncAttributeMaxDynamicSharedMemorySize, GEMM_SMEM);
    cudaFuncSetAttribute((const void*)mm_gemm<2>,
                         cudaFuncAttributeMaxDynamicSharedMemorySize, GEMM_SMEM);

    cvt_kernel<<<(3*NC*NC + 255)/256, 256>>>(qkv_w,  wqh, wql, 3*NC*NC);
    cvt_kernel<<<(NC*NC   + 255)/256, 256>>>(inl_w,  wih, wil, NC*NC);
    cvt_kernel<<<(NC*NC   + 255)/256, 256>>>(proj_w, wph, wpl, NC*NC);
    gn_stats1<<<512, 256>>>(x);
    gn_stats2<<<1, 64>>>();
    gn_apply<<<dim3(16, 8, 8), 256>>>(x, gns, gnb);

    mm_gemm<0><<<dim3(12, 64), 256, GEMM_SMEM>>>(hh, hl, wqh, wql, qkv_b,
                                                 nullptr, nullptr, nullptr, nullptr);
    attn_kernel<<<dim3(8, 8, 8), 256, ATT_SMEM>>>();
    mm_gemm<1><<<dim3(4, 64), 256, GEMM_SMEM>>>(hfh, hfl, wih, wil, inl_b,
                                                nullptr, nullptr, hf2h, hf2l);
    mm_gemm<1><<<dim3(4, 64), 256, GEMM_SMEM>>>(hf2h, hf2l, wih, wil, inl_b,
                                                nullptr, nullptr, hfh, hfl);
    mm_gemm<1><<<dim3(4, 64), 256, GEMM_SMEM>>>(hfh, hfl, wih, wil, inl_b,
                                                nullptr, nullptr, hf2h, hf2l);
    mm_gemm<2><<<dim3(4, 64), 256, GEMM_SMEM>>>(hf2h, hf2l, wph, wpl, proj_b,
                                                x, out, nullptr, nullptr);
}

// round 7
// speedup vs baseline: 3.9160x; 1.3241x over previous
#include <cuda_runtime.h>
#include <cuda_fp16.h>
#include <math.h>
#include <cstdint>

#define NB 8
#define NC 512
#define NS 1024
#define NHD 8
#define HD 64
#define QSCALE 0.180336540f   // 0.125 * log2(e), applied to S in fp32

// ---- scratch (static __device__, no allocs) ----
__device__ __half g_h_hi [NB*NS*NC];
__device__ __half g_h_lo [NB*NS*NC];
__device__ __half g_qh[NB*NHD*NS*HD], g_ql[NB*NHD*NS*HD];
__device__ __half g_kh[NB*NHD*NS*HD];
__device__ __half g_vh[NB*NHD*NS*HD];
__device__ __half g_hf_hi [NB*NS*NC];
__device__ __half g_hf_lo [NB*NS*NC];
__device__ __half g_hf2_hi[NB*NS*NC];
__device__ __half g_hf2_lo[NB*NS*NC];
__device__ __half g_wq_hi[3*NC*NC];
__device__ __half g_wi_hi[NC*NC];
__device__ __half g_wp_hi[NC*NC];
__device__ float2 g_part[512];
__device__ float2 g_stat[64];

__device__ __forceinline__ uint32_t smem_u32(const void* p) {
    uint32_t a;
    asm("{ .reg .u64 t; cvta.to.shared.u64 t, %1; cvt.u32.u64 %0, t; }" : "=r"(a) : "l"(p));
    return a;
}
__device__ __forceinline__ void cp16(uint32_t dst, const void* src) {
    asm volatile("cp.async.cg.shared.global [%0], [%1], 16;" :: "r"(dst), "l"(src));
}
#define CP_COMMIT() asm volatile("cp.async.commit_group;" ::: "memory")
#define CP_WAIT1()  asm volatile("cp.async.wait_group 1;" ::: "memory")
#define CP_WAIT0()  asm volatile("cp.async.wait_group 0;" ::: "memory")
__device__ __forceinline__ void ldsm4(uint32_t& r0, uint32_t& r1, uint32_t& r2,
                                      uint32_t& r3, uint32_t addr) {
    asm volatile("ldmatrix.sync.aligned.m8n8.x4.shared.b16 {%0,%1,%2,%3}, [%4];"
                 : "=r"(r0), "=r"(r1), "=r"(r2), "=r"(r3) : "r"(addr));
}
__device__ __forceinline__ void ldsm4t(uint32_t& r0, uint32_t& r1, uint32_t& r2,
                                       uint32_t& r3, uint32_t addr) {
    asm volatile("ldmatrix.sync.aligned.m8n8.x4.trans.shared.b16 {%0,%1,%2,%3}, [%4];"
                 : "=r"(r0), "=r"(r1), "=r"(r2), "=r"(r3) : "r"(addr));
}
__device__ __forceinline__ void mma16816(float* d, const uint32_t* a, const uint32_t* b) {
    asm volatile("mma.sync.aligned.m16n8k16.row.col.f32.f16.f16.f32 "
        "{%0,%1,%2,%3},{%4,%5,%6,%7},{%8,%9},{%0,%1,%2,%3};"
        : "+f"(d[0]), "+f"(d[1]), "+f"(d[2]), "+f"(d[3])
        : "r"(a[0]), "r"(a[1]), "r"(a[2]), "r"(a[3]), "r"(b[0]), "r"(b[1]));
}
__device__ __forceinline__ uint32_t packh2(float a, float b) {
    __half2 t = __floats2half2_rn(a, b);
    return *(uint32_t*)&t;
}

// ============================================================
// weight fp32 -> fp16 (hi only)
// ============================================================
__global__ void cvt_kernel(const float* __restrict__ src,
                           __half* __restrict__ hi, int n) {
    int i = blockIdx.x * 256 + threadIdx.x;
    if (i < n) hi[i] = __float2half_rn(src[i]);
}

// ============================================================
// GroupNorm, 3-stage
// ============================================================
__global__ void gn_stats1(const float* __restrict__ x) {
    int bg = blockIdx.x >> 3, chunk = blockIdx.x & 7;
    const float4* xp = (const float4*)(x + (size_t)bg*65536 + chunk*8192);
    int tid = threadIdx.x;
    float s1 = 0.f, s2 = 0.f;
#pragma unroll
    for (int it = 0; it < 8; it++) {
        float4 v = xp[tid + it*256];
        s1 += v.x + v.y + v.z + v.w;
        s2 += v.x*v.x + v.y*v.y + v.z*v.z + v.w*v.w;
    }
    __shared__ float r1[256], r2[256];
    r1[tid] = s1; r2[tid] = s2;
    __syncthreads();
    for (int o = 128; o > 0; o >>= 1) {
        if (tid < o) { r1[tid] += r1[tid+o]; r2[tid] += r2[tid+o]; }
        __syncthreads();
    }
    if (tid == 0) g_part[blockIdx.x] = make_float2(r1[0], r2[0]);
}
__global__ void gn_stats2() {
    int g = threadIdx.x;
    float s1 = 0.f, s2 = 0.f;
#pragma unroll
    for (int i = 0; i < 8; i++) {
        float2 p = g_part[g*8 + i];
        s1 += p.x; s2 += p.y;
    }
    float mean = s1 * (1.f/65536.f);
    float var  = s2 * (1.f/65536.f) - mean*mean;
    g_stat[g] = make_float2(mean, rsqrtf(var + 1e-5f));
}
__global__ void gn_apply(const float* __restrict__ x,
                         const float* __restrict__ gns,
                         const float* __restrict__ gnb) {
    __shared__ float tile[64][65];
    int sp0 = blockIdx.x << 6, c0 = blockIdx.y << 6, b = blockIdx.z;
    int tid = threadIdx.x;
    float2 st = g_stat[b*8 + blockIdx.y];
    int cl_l = tid >> 6, sp_l = tid & 63;
#pragma unroll
    for (int it = 0; it < 16; it++) {
        int cl = it*4 + cl_l;
        float v = x[(size_t)(b*NC + c0 + cl)*NS + sp0 + sp_l];
        tile[cl][sp_l] = (v - st.x) * st.y * gns[c0 + cl] + gnb[c0 + cl];
    }
    __syncthreads();
    int cc = tid & 63;
#pragma unroll
    for (int it = 0; it < 16; it++) {
        int sp = it*4 + (tid >> 6);
        float v = tile[cc][sp];
        size_t idx = (size_t)(b*NS + sp0 + sp)*NC + c0 + cc;
        __half h = __float2half_rn(v);
        g_h_hi[idx] = h;
        g_h_lo[idx] = __float2half_rn(v - __half2float(h));
    }
}

// ============================================================
// mma.sync fp16 2-term GEMM: D = Ah*Wh + Al*Wh (weights hi-only)
// CTA 128x128, BK=64, cp.async double-buffered.
// MODE 0: qkv scatter  MODE 1: INL tanh  MODE 2: proj+residual
// ============================================================
#define PITCH_B 144
#define STG_AL  (128*PITCH_B)       // Al tile
#define STG_B   (2*128*PITCH_B)     // Wh tile
#define STAGE_BYTES (3*128*PITCH_B) // 55296
#define GEMM_SMEM (2*STAGE_BYTES)   // 110592

template<int MODE>
__global__ void __launch_bounds__(256, 1)
mm_gemm(const __half* __restrict__ Ah, const __half* __restrict__ Al,
        const __half* __restrict__ Wh,
        const float* __restrict__ bias,
        const float* __restrict__ addsrc, float* __restrict__ out,
        __half* __restrict__ ohi, __half* __restrict__ olo)
{
    extern __shared__ char smem[];
    uint32_t sb = smem_u32(smem);
    int tid = threadIdx.x, lane = tid & 31, wid = tid >> 5;
    int wm = wid >> 2, wn = wid & 3;
    int n0 = blockIdx.x << 7, m0 = blockIdx.y << 7;

    float D[4][4][4] = {};

    auto load_stage = [&](int s, int bb) {
        int k0 = s << 6;
        uint32_t base = sb + bb*STAGE_BYTES;
#pragma unroll
        for (int it = 0; it < 4; it++) {
            int chunk = tid + it*256;
            int r = chunk >> 3, c = chunk & 7;
            size_t ga = (size_t)(m0 + r)*NC + k0 + c*8;
            size_t gb = (size_t)(n0 + r)*NC + k0 + c*8;
            uint32_t so = r*PITCH_B + c*16;
            cp16(base + so,          Ah + ga);
            cp16(base + STG_AL + so, Al + ga);
            cp16(base + STG_B  + so, Wh + gb);
        }
        CP_COMMIT();
    };

    uint32_t aOff = (uint32_t)(wm*64 + (lane & 15))*PITCH_B + (lane >> 4)*16;
    uint32_t bOff = (uint32_t)STG_B
                  + (uint32_t)(wn*32 + ((lane >> 4) & 1)*8 + (lane & 7))*PITCH_B
                  + ((lane >> 3) & 1)*16;

    load_stage(0, 0);

    int buf = 0;
    for (int s = 0; s < 8; s++) {
        if (s < 7) { load_stage(s + 1, buf ^ 1); CP_WAIT1(); }
        else       { CP_WAIT0(); }
        __syncthreads();
        uint32_t base = sb + buf*STAGE_BYTES;
#pragma unroll
        for (int ks = 0; ks < 4; ks++) {
            uint32_t ah[4][4], al[4][4], bh[2][4];
#pragma unroll
            for (int i = 0; i < 4; i++) {
                uint32_t adr = base + aOff + i*(16*PITCH_B) + ks*32;
                ldsm4(ah[i][0], ah[i][1], ah[i][2], ah[i][3], adr);
                ldsm4(al[i][0], al[i][1], al[i][2], al[i][3], adr + STG_AL);
            }
#pragma unroll
            for (int j2 = 0; j2 < 2; j2++) {
                uint32_t adr = base + bOff + j2*(16*PITCH_B) + ks*32;
                ldsm4(bh[j2][0], bh[j2][1], bh[j2][2], bh[j2][3], adr);
            }
#pragma unroll
            for (int i = 0; i < 4; i++)
#pragma unroll
                for (int j2 = 0; j2 < 2; j2++) {
                    mma16816(D[i][2*j2],   ah[i], &bh[j2][0]);
                    mma16816(D[i][2*j2],   al[i], &bh[j2][0]);
                    mma16816(D[i][2*j2+1], ah[i], &bh[j2][2]);
                    mma16816(D[i][2*j2+1], al[i], &bh[j2][2]);
                }
        }
        __syncthreads();
        buf ^= 1;
    }

    int g = lane >> 2, tig = lane & 3;
#pragma unroll
    for (int i = 0; i < 4; i++) {
#pragma unroll
        for (int j = 0; j < 4; j++) {
            int Cn = n0 + wn*32 + j*8 + tig*2;
            float b0 = bias[Cn], b1 = bias[Cn+1];
#pragma unroll
            for (int hr = 0; hr < 2; hr++) {
                int R = m0 + wm*64 + i*16 + g + hr*8;
                float v0 = D[i][j][hr*2+0] + b0;
                float v1 = D[i][j][hr*2+1] + b1;
                if (MODE == 0) {
                    int b = R >> 10, sp = R & 1023;
                    int which = Cn >> 9, head = (Cn >> 6) & 7, d = Cn & 63;
                    size_t idx = (size_t)((b*NHD + head)*NS + sp)*HD + d;
                    if (which == 0) {
                        __half h0 = __float2half_rn(v0);
                        __half h1 = __float2half_rn(v1);
                        __half2 hp; hp.x = h0; hp.y = h1;
                        *(__half2*)(g_qh + idx) = hp;
                        __half2 lp;
                        lp.x = __float2half_rn(v0 - __half2float(h0));
                        lp.y = __float2half_rn(v1 - __half2float(h1));
                        *(__half2*)(g_ql + idx) = lp;
                    } else {
                        __half* dst = (which == 1) ? g_kh : g_vh;
                        *(__half2*)(dst + idx) = __floats2half2_rn(v0, v1);
                    }
                } else if (MODE == 1) {
                    size_t idx = (size_t)R*NC + Cn;
                    __half2 sh = *(const __half2*)(Ah + idx);
                    __half2 sl = *(const __half2*)(Al + idx);
                    float a0 = __half2float(sh.x) + __half2float(sl.x);
                    float a1 = __half2float(sh.y) + __half2float(sl.y);
                    float r0 = a0 + 0.1f*tanhf(v0);
                    float r1 = a1 + 0.1f*tanhf(v1);
                    __half h0 = __float2half_rn(r0);
                    __half h1 = __float2half_rn(r1);
                    __half2 hp; hp.x = h0; hp.y = h1;
                    *(__half2*)(ohi + idx) = hp;
                    __half2 lp;
                    lp.x = __float2half_rn(r0 - __half2float(h0));
                    lp.y = __float2half_rn(r1 - __half2float(h1));
                    *(__half2*)(olo + idx) = lp;
                } else {
                    int b = R >> 10, sp = R & 1023;
                    size_t basei = (size_t)(b*NC + Cn)*NS + sp;
                    out[basei     ] = addsrc[basei     ] + v0;
                    out[basei + NS] = addsrc[basei + NS] + v1;
                }
            }
        }
    }
}

// ============================================================
// FA2 mma.sync fp16 attention: Q 2-term (hi/lo), K/V hi-only.
// S scaled by QSCALE in fp32; softmax base-2.
// ============================================================
#define APITCH 144
#define ATILE  (128*APITCH)          // 18432 bytes
#define ABUF   (2*ATILE)             // Kh | Vh
#define ATT_SMEM (2*ABUF)            // 73728

__global__ void __launch_bounds__(256, 1) attn_kernel() {
    extern __shared__ char smem[];
    uint32_t sb = smem_u32(smem);
    int tid = threadIdx.x, lane = tid & 31, w = tid >> 5;
    int qt = blockIdx.x, h = blockIdx.y, b = blockIdx.z;
    int g = lane >> 2, tig = lane & 3;
    size_t bh_off = (size_t)(b*NHD + h)*NS*HD;

    const __half* Kh = g_kh + bh_off;
    const __half* Vh = g_vh + bh_off;

    auto load_kv = [&](int kt, int bb) {
        size_t t0HD = (size_t)(kt << 7) * HD;
        uint32_t base = sb + bb*ABUF;
#pragma unroll
        for (int it = 0; it < 4; it++) {
            int chunk = tid + it*256;
            int r = chunk >> 3, c = chunk & 7;
            uint32_t so = r*APITCH + c*16;
            size_t goff = t0HD + (size_t)r*HD + c*8;
            cp16(base + so,         Kh + goff);
            cp16(base + ATILE + so, Vh + goff);
        }
        CP_COMMIT();
    };

    load_kv(0, 0);

    // ---- Q frags direct from gmem (hi/lo) ----
    uint32_t qh[4][4], ql[4][4];
    {
        const __half* Qh = g_qh + bh_off + (size_t)(qt<<7)*HD;
        const __half* Ql = g_ql + bh_off + (size_t)(qt<<7)*HD;
        int r0 = w*16 + g;
#pragma unroll
        for (int ks = 0; ks < 4; ks++) {
            int c0 = ks*16 + tig*2;
            qh[ks][0] = *(const uint32_t*)(Qh + (size_t)r0*HD + c0);
            qh[ks][1] = *(const uint32_t*)(Qh + (size_t)(r0+8)*HD + c0);
            qh[ks][2] = *(const uint32_t*)(Qh + (size_t)r0*HD + c0 + 8);
            qh[ks][3] = *(const uint32_t*)(Qh + (size_t)(r0+8)*HD + c0 + 8);
            ql[ks][0] = *(const uint32_t*)(Ql + (size_t)r0*HD + c0);
            ql[ks][1] = *(const uint32_t*)(Ql + (size_t)(r0+8)*HD + c0);
            ql[ks][2] = *(const uint32_t*)(Ql + (size_t)r0*HD + c0 + 8);
            ql[ks][3] = *(const uint32_t*)(Ql + (size_t)(r0+8)*HD + c0 + 8);
        }
    }

    float O[8][4] = {};
    float m0 = -1e30f, m1 = -1e30f, l0 = 0.f, l1 = 0.f;

    uint32_t kOff = (uint32_t)(((lane >> 4) & 1)*8 + (lane & 7))*APITCH
                  + ((lane >> 3) & 1)*16;
    uint32_t vOff = (uint32_t)ATILE
                  + (uint32_t)(((lane >> 3) & 1)*8 + (lane & 7))*APITCH
                  + ((lane >> 4) & 1)*16;

    int buf = 0;
    for (int kt = 0; kt < 8; kt++) {
        if (kt < 7) { load_kv(kt + 1, buf ^ 1); CP_WAIT1(); }
        else        { CP_WAIT0(); }
        __syncthreads();
        uint32_t base = sb + buf*ABUF;

        // ---- S = Q K^T (2-term) ----
        float S[16][4];
#pragma unroll
        for (int i = 0; i < 16; i++) { S[i][0]=0.f; S[i][1]=0.f; S[i][2]=0.f; S[i][3]=0.f; }
#pragma unroll
        for (int ks = 0; ks < 4; ks++) {
#pragma unroll
            for (int nf = 0; nf < 8; nf++) {
                uint32_t kh4[4];
                uint32_t adr = base + kOff + nf*(16*APITCH) + ks*32;
                ldsm4(kh4[0], kh4[1], kh4[2], kh4[3], adr);
                mma16816(S[2*nf],   qh[ks], &kh4[0]);
                mma16816(S[2*nf],   ql[ks], &kh4[0]);
                mma16816(S[2*nf+1], qh[ks], &kh4[2]);
                mma16816(S[2*nf+1], ql[ks], &kh4[2]);
            }
        }
        // fp32 scale (keeps Q unscaled in fp16 range)
#pragma unroll
        for (int i = 0; i < 16; i++) {
            S[i][0] *= QSCALE; S[i][1] *= QSCALE;
            S[i][2] *= QSCALE; S[i][3] *= QSCALE;
        }

        // ---- softmax (base-2) ----
        float mx0 = -1e30f, mx1 = -1e30f;
#pragma unroll
        for (int i = 0; i < 16; i++) {
            mx0 = fmaxf(mx0, fmaxf(S[i][0], S[i][1]));
            mx1 = fmaxf(mx1, fmaxf(S[i][2], S[i][3]));
        }
        mx0 = fmaxf(mx0, __shfl_xor_sync(0xffffffff, mx0, 1));
        mx0 = fmaxf(mx0, __shfl_xor_sync(0xffffffff, mx0, 2));
        mx1 = fmaxf(mx1, __shfl_xor_sync(0xffffffff, mx1, 1));
        mx1 = fmaxf(mx1, __shfl_xor_sync(0xffffffff, mx1, 2));
        float mn0 = fmaxf(m0, mx0), mn1 = fmaxf(m1, mx1);
        float al0 = exp2f(m0 - mn0), al1 = exp2f(m1 - mn1);
        m0 = mn0; m1 = mn1;
        float sum0 = 0.f, sum1 = 0.f;
#pragma unroll
        for (int i = 0; i < 16; i++) {
            S[i][0] = exp2f(S[i][0] - mn0);
            S[i][1] = exp2f(S[i][1] - mn0);
            S[i][2] = exp2f(S[i][2] - mn1);
            S[i][3] = exp2f(S[i][3] - mn1);
            sum0 += S[i][0] + S[i][1];
            sum1 += S[i][2] + S[i][3];
        }
        sum0 += __shfl_xor_sync(0xffffffff, sum0, 1);
        sum0 += __shfl_xor_sync(0xffffffff, sum0, 2);
        sum1 += __shfl_xor_sync(0xffffffff, sum1, 1);
        sum1 += __shfl_xor_sync(0xffffffff, sum1, 2);
        l0 = l0*al0 + sum0;
        l1 = l1*al1 + sum1;
#pragma unroll
        for (int of = 0; of < 8; of++) {
            O[of][0]*=al0; O[of][1]*=al0; O[of][2]*=al1; O[of][3]*=al1;
        }

        // ---- O += P V (2-term: P hi/lo, V hi) ----
#pragma unroll
        for (int t16 = 0; t16 < 8; t16++) {
            float* c0 = S[2*t16];
            float* c1 = S[2*t16+1];
            uint32_t pha[4], pla[4];
            {
                __half h00 = __float2half_rn(c0[0]);
                __half h01 = __float2half_rn(c0[1]);
                __half h02 = __float2half_rn(c0[2]);
                __half h03 = __float2half_rn(c0[3]);
                __half h10 = __float2half_rn(c1[0]);
                __half h11 = __float2half_rn(c1[1]);
                __half h12 = __float2half_rn(c1[2]);
                __half h13 = __float2half_rn(c1[3]);
                __half2 t;
                t.x=h00; t.y=h01; pha[0]=*(uint32_t*)&t;
                t.x=h02; t.y=h03; pha[1]=*(uint32_t*)&t;
                t.x=h10; t.y=h11; pha[2]=*(uint32_t*)&t;
                t.x=h12; t.y=h13; pha[3]=*(uint32_t*)&t;
                pla[0] = packh2(c0[0]-__half2float(h00), c0[1]-__half2float(h01));
                pla[1] = packh2(c0[2]-__half2float(h02), c0[3]-__half2float(h03));
                pla[2] = packh2(c1[0]-__half2float(h10), c1[1]-__half2float(h11));
                pla[3] = packh2(c1[2]-__half2float(h12), c1[3]-__half2float(h13));
            }
#pragma unroll
            for (int db = 0; db < 4; db++) {
                uint32_t vh4[4];
                uint32_t adr = base + vOff + t16*(16*APITCH) + db*32;
                ldsm4t(vh4[0], vh4[1], vh4[2], vh4[3], adr);
                mma16816(O[2*db],   pha, &vh4[0]);
                mma16816(O[2*db],   pla, &vh4[0]);
                mma16816(O[2*db+1], pha, &vh4[2]);
                mma16816(O[2*db+1], pla, &vh4[2]);
            }
        }
        __syncthreads();
        buf ^= 1;
    }

    // ---- epilogue ----
    float inv0 = 1.f / l0, inv1 = 1.f / l1;
    int r0g = (qt<<7) + w*16 + g;
#pragma unroll
    for (int of = 0; of < 8; of++) {
        int d0 = of*8 + tig*2;
        float a0 = O[of][0]*inv0, a1 = O[of][1]*inv0;
        float a2 = O[of][2]*inv1, a3 = O[of][3]*inv1;
        size_t i0 = (size_t)(b*NS + r0g)*NC + h*HD + d0;
        size_t i1 = (size_t)(b*NS + r0g + 8)*NC + h*HD + d0;
        __half h0 = __float2half_rn(a0), h1 = __float2half_rn(a1);
        __half h2 = __float2half_rn(a2), h3 = __float2half_rn(a3);
        __half2 p;
        p.x=h0; p.y=h1; *(__half2*)(g_hf_hi + i0) = p;
        p.x=h2; p.y=h3; *(__half2*)(g_hf_hi + i1) = p;
        p.x=__float2half_rn(a0-__half2float(h0));
        p.y=__float2half_rn(a1-__half2float(h1));
        *(__half2*)(g_hf_lo + i0) = p;
        p.x=__float2half_rn(a2-__half2float(h2));
        p.y=__float2half_rn(a3-__half2float(h3));
        *(__half2*)(g_hf_lo + i1) = p;
    }
}

// ============================================================
// launch
// ============================================================
extern "C" void kernel_launch(void* const* d_in, const int* in_sizes, int n_in,
                              void* d_out, int out_size) {
    const float* x      = (const float*)d_in[0];
    const float* gns    = (const float*)d_in[1];
    const float* gnb    = (const float*)d_in[2];
    const float* qkv_w  = (const float*)d_in[3];
    const float* qkv_b  = (const float*)d_in[4];
    const float* proj_w = (const float*)d_in[5];
    const float* proj_b = (const float*)d_in[6];
    const float* inl_w  = (const float*)d_in[7];
    const float* inl_b  = (const float*)d_in[8];
    float* out = (float*)d_out;

    __half *hh, *hl, *wqh, *wih, *wph;
    __half *hfh, *hfl, *hf2h, *hf2l;
    cudaGetSymbolAddress((void**)&hh,   g_h_hi);
    cudaGetSymbolAddress((void**)&hl,   g_h_lo);
    cudaGetSymbolAddress((void**)&wqh,  g_wq_hi);
    cudaGetSymbolAddress((void**)&wih,  g_wi_hi);
    cudaGetSymbolAddress((void**)&wph,  g_wp_hi);
    cudaGetSymbolAddress((void**)&hfh,  g_hf_hi);
    cudaGetSymbolAddress((void**)&hfl,  g_hf_lo);
    cudaGetSymbolAddress((void**)&hf2h, g_hf2_hi);
    cudaGetSymbolAddress((void**)&hf2l, g_hf2_lo);

    cudaFuncSetAttribute((const void*)attn_kernel,
                         cudaFuncAttributeMaxDynamicSharedMemorySize, ATT_SMEM);
    cudaFuncSetAttribute((const void*)mm_gemm<0>,
                         cudaFuncAttributeMaxDynamicSharedMemorySize, GEMM_SMEM);
    cudaFuncSetAttribute((const void*)mm_gemm<1>,
                         cudaFuncAttributeMaxDynamicSharedMemorySize, GEMM_SMEM);
    cudaFuncSetAttribute((const void*)mm_gemm<2>,
                         cudaFuncAttributeMaxDynamicSharedMemorySize, GEMM_SMEM);

    cvt_kernel<<<(3*NC*NC + 255)/256, 256>>>(qkv_w,  wqh, 3*NC*NC);
    cvt_kernel<<<(NC*NC   + 255)/256, 256>>>(inl_w,  wih, NC*NC);
    cvt_kernel<<<(NC*NC   + 255)/256, 256>>>(proj_w, wph, NC*NC);
    gn_stats1<<<512, 256>>>(x);
    gn_stats2<<<1, 64>>>();
    gn_apply<<<dim3(16, 8, 8), 256>>>(x, gns, gnb);

    mm_gemm<0><<<dim3(12, 64), 256, GEMM_SMEM>>>(hh, hl, wqh, qkv_b,
                                                 nullptr, nullptr, nullptr, nullptr);
    attn_kernel<<<dim3(8, 8, 8), 256, ATT_SMEM>>>();
    mm_gemm<1><<<dim3(4, 64), 256, GEMM_SMEM>>>(hfh, hfl, wih, inl_b,
                                                nullptr, nullptr, hf2h, hf2l);
    mm_gemm<1><<<dim3(4, 64), 256, GEMM_SMEM>>>(hf2h, hf2l, wih, inl_b,
                                                nullptr, nullptr, hfh, hfl);
    mm_gemm<1><<<dim3(4, 64), 256, GEMM_SMEM>>>(hfh, hfl, wih, inl_b,
                                                nullptr, nullptr, hf2h, hf2l);
    mm_gemm<2><<<dim3(4, 64), 256, GEMM_SMEM>>>(hf2h, hf2l, wph, proj_b,
                                                x, out, nullptr, nullptr);
}

// round 8
// speedup vs baseline: 5.9820x; 1.5276x over previous
#include <cuda_runtime.h>
#include <cuda_fp16.h>
#include <math.h>
#include <cstdint>

#define NB 8
#define NC 512
#define NS 1024
#define NHD 8
#define HD 64
#define QSCALE 0.180336540f   // 0.125 * log2(e), applied to S in fp32

// ---- scratch (static __device__, no allocs) ----
__device__ __half g_h_hi [NB*NS*NC];
__device__ __half g_qh[NB*NHD*NS*HD];
__device__ __half g_kh[NB*NHD*NS*HD];
__device__ __half g_vh[NB*NHD*NS*HD];
__device__ __half g_hf_hi [NB*NS*NC];
__device__ __half g_hf_lo [NB*NS*NC];   // storage-only lo (residual stream)
__device__ __half g_hf2_hi[NB*NS*NC];
__device__ __half g_hf2_lo[NB*NS*NC];
__device__ __half g_wq_hi[3*NC*NC];
__device__ __half g_wi_hi[NC*NC];
__device__ __half g_wp_hi[NC*NC];
__device__ float2 g_part[512];
__device__ float2 g_stat[64];

__device__ __forceinline__ uint32_t smem_u32(const void* p) {
    uint32_t a;
    asm("{ .reg .u64 t; cvta.to.shared.u64 t, %1; cvt.u32.u64 %0, t; }" : "=r"(a) : "l"(p));
    return a;
}
__device__ __forceinline__ void cp16(uint32_t dst, const void* src) {
    asm volatile("cp.async.cg.shared.global [%0], [%1], 16;" :: "r"(dst), "l"(src));
}
#define CP_COMMIT() asm volatile("cp.async.commit_group;" ::: "memory")
#define CP_WAIT1()  asm volatile("cp.async.wait_group 1;" ::: "memory")
#define CP_WAIT0()  asm volatile("cp.async.wait_group 0;" ::: "memory")
__device__ __forceinline__ void ldsm4(uint32_t& r0, uint32_t& r1, uint32_t& r2,
                                      uint32_t& r3, uint32_t addr) {
    asm volatile("ldmatrix.sync.aligned.m8n8.x4.shared.b16 {%0,%1,%2,%3}, [%4];"
                 : "=r"(r0), "=r"(r1), "=r"(r2), "=r"(r3) : "r"(addr));
}
__device__ __forceinline__ void ldsm4t(uint32_t& r0, uint32_t& r1, uint32_t& r2,
                                       uint32_t& r3, uint32_t addr) {
    asm volatile("ldmatrix.sync.aligned.m8n8.x4.trans.shared.b16 {%0,%1,%2,%3}, [%4];"
                 : "=r"(r0), "=r"(r1), "=r"(r2), "=r"(r3) : "r"(addr));
}
__device__ __forceinline__ void mma16816(float* d, const uint32_t* a, const uint32_t* b) {
    asm volatile("mma.sync.aligned.m16n8k16.row.col.f32.f16.f16.f32 "
        "{%0,%1,%2,%3},{%4,%5,%6,%7},{%8,%9},{%0,%1,%2,%3};"
        : "+f"(d[0]), "+f"(d[1]), "+f"(d[2]), "+f"(d[3])
        : "r"(a[0]), "r"(a[1]), "r"(a[2]), "r"(a[3]), "r"(b[0]), "r"(b[1]));
}

// ============================================================
// weight fp32 -> fp16
// ============================================================
__global__ void cvt_kernel(const float* __restrict__ src,
                           __half* __restrict__ hi, int n) {
    int i = blockIdx.x * 256 + threadIdx.x;
    if (i < n) hi[i] = __float2half_rn(src[i]);
}

// ============================================================
// GroupNorm, 3-stage
// ============================================================
__global__ void gn_stats1(const float* __restrict__ x) {
    int bg = blockIdx.x >> 3, chunk = blockIdx.x & 7;
    const float4* xp = (const float4*)(x + (size_t)bg*65536 + chunk*8192);
    int tid = threadIdx.x;
    float s1 = 0.f, s2 = 0.f;
#pragma unroll
    for (int it = 0; it < 8; it++) {
        float4 v = xp[tid + it*256];
        s1 += v.x + v.y + v.z + v.w;
        s2 += v.x*v.x + v.y*v.y + v.z*v.z + v.w*v.w;
    }
    __shared__ float r1[256], r2[256];
    r1[tid] = s1; r2[tid] = s2;
    __syncthreads();
    for (int o = 128; o > 0; o >>= 1) {
        if (tid < o) { r1[tid] += r1[tid+o]; r2[tid] += r2[tid+o]; }
        __syncthreads();
    }
    if (tid == 0) g_part[blockIdx.x] = make_float2(r1[0], r2[0]);
}
__global__ void gn_stats2() {
    int g = threadIdx.x;
    float s1 = 0.f, s2 = 0.f;
#pragma unroll
    for (int i = 0; i < 8; i++) {
        float2 p = g_part[g*8 + i];
        s1 += p.x; s2 += p.y;
    }
    float mean = s1 * (1.f/65536.f);
    float var  = s2 * (1.f/65536.f) - mean*mean;
    g_stat[g] = make_float2(mean, rsqrtf(var + 1e-5f));
}
__global__ void gn_apply(const float* __restrict__ x,
                         const float* __restrict__ gns,
                         const float* __restrict__ gnb) {
    __shared__ float tile[64][65];
    int sp0 = blockIdx.x << 6, c0 = blockIdx.y << 6, b = blockIdx.z;
    int tid = threadIdx.x;
    float2 st = g_stat[b*8 + blockIdx.y];
    int cl_l = tid >> 6, sp_l = tid & 63;
#pragma unroll
    for (int it = 0; it < 16; it++) {
        int cl = it*4 + cl_l;
        float v = x[(size_t)(b*NC + c0 + cl)*NS + sp0 + sp_l];
        tile[cl][sp_l] = (v - st.x) * st.y * gns[c0 + cl] + gnb[c0 + cl];
    }
    __syncthreads();
    int cc = tid & 63;
#pragma unroll
    for (int it = 0; it < 16; it++) {
        int sp = it*4 + (tid >> 6);
        size_t idx = (size_t)(b*NS + sp0 + sp)*NC + c0 + cc;
        g_h_hi[idx] = __float2half_rn(tile[cc][sp]);
    }
}

// ============================================================
// mma.sync fp16 1-term GEMM: D = Ah*Wh
// CTA 128x128, BK=64, cp.async double-buffered, 2 CTAs/SM.
// MODE 0: qkv scatter  MODE 1: INL tanh (residual = Alo storage pair)
// MODE 2: proj+residual
// ============================================================
#define PITCH_B 144
#define STG_B   (128*PITCH_B)        // 18432: Wh tile offset
#define STAGE_BYTES (2*128*PITCH_B)  // 36864
#define GEMM_SMEM (2*STAGE_BYTES)    // 73728

template<int MODE>
__global__ void __launch_bounds__(256, 2)
mm_gemm(const __half* __restrict__ Ah, const __half* __restrict__ Alo,
        const __half* __restrict__ Wh,
        const float* __restrict__ bias,
        const float* __restrict__ addsrc, float* __restrict__ out,
        __half* __restrict__ ohi, __half* __restrict__ olo)
{
    extern __shared__ char smem[];
    uint32_t sb = smem_u32(smem);
    int tid = threadIdx.x, lane = tid & 31, wid = tid >> 5;
    int wm = wid >> 2, wn = wid & 3;
    int n0 = blockIdx.x << 7, m0 = blockIdx.y << 7;

    float D[4][4][4] = {};

    auto load_stage = [&](int s, int bb) {
        int k0 = s << 6;
        uint32_t base = sb + bb*STAGE_BYTES;
#pragma unroll
        for (int it = 0; it < 4; it++) {
            int chunk = tid + it*256;
            int r = chunk >> 3, c = chunk & 7;
            size_t ga = (size_t)(m0 + r)*NC + k0 + c*8;
            size_t gb = (size_t)(n0 + r)*NC + k0 + c*8;
            uint32_t so = r*PITCH_B + c*16;
            cp16(base + so,         Ah + ga);
            cp16(base + STG_B + so, Wh + gb);
        }
        CP_COMMIT();
    };

    uint32_t aOff = (uint32_t)(wm*64 + (lane & 15))*PITCH_B + (lane >> 4)*16;
    uint32_t bOff = (uint32_t)STG_B
                  + (uint32_t)(wn*32 + ((lane >> 4) & 1)*8 + (lane & 7))*PITCH_B
                  + ((lane >> 3) & 1)*16;

    load_stage(0, 0);

    int buf = 0;
    for (int s = 0; s < 8; s++) {
        if (s < 7) { load_stage(s + 1, buf ^ 1); CP_WAIT1(); }
        else       { CP_WAIT0(); }
        __syncthreads();
        uint32_t base = sb + buf*STAGE_BYTES;
#pragma unroll
        for (int ks = 0; ks < 4; ks++) {
            uint32_t ah[4][4], bh[2][4];
#pragma unroll
            for (int i = 0; i < 4; i++) {
                uint32_t adr = base + aOff + i*(16*PITCH_B) + ks*32;
                ldsm4(ah[i][0], ah[i][1], ah[i][2], ah[i][3], adr);
            }
#pragma unroll
            for (int j2 = 0; j2 < 2; j2++) {
                uint32_t adr = base + bOff + j2*(16*PITCH_B) + ks*32;
                ldsm4(bh[j2][0], bh[j2][1], bh[j2][2], bh[j2][3], adr);
            }
#pragma unroll
            for (int i = 0; i < 4; i++)
#pragma unroll
                for (int j2 = 0; j2 < 2; j2++) {
                    mma16816(D[i][2*j2],   ah[i], &bh[j2][0]);
                    mma16816(D[i][2*j2+1], ah[i], &bh[j2][2]);
                }
        }
        __syncthreads();
        buf ^= 1;
    }

    int g = lane >> 2, tig = lane & 3;
#pragma unroll
    for (int i = 0; i < 4; i++) {
#pragma unroll
        for (int j = 0; j < 4; j++) {
            int Cn = n0 + wn*32 + j*8 + tig*2;
            float b0 = bias[Cn], b1 = bias[Cn+1];
#pragma unroll
            for (int hr = 0; hr < 2; hr++) {
                int R = m0 + wm*64 + i*16 + g + hr*8;
                float v0 = D[i][j][hr*2+0] + b0;
                float v1 = D[i][j][hr*2+1] + b1;
                if (MODE == 0) {
                    int b = R >> 10, sp = R & 1023;
                    int which = Cn >> 9, head = (Cn >> 6) & 7, d = Cn & 63;
                    size_t idx = (size_t)((b*NHD + head)*NS + sp)*HD + d;
                    __half* dst = (which == 0) ? g_qh : (which == 1) ? g_kh : g_vh;
                    *(__half2*)(dst + idx) = __floats2half2_rn(v0, v1);
                } else if (MODE == 1) {
                    size_t idx = (size_t)R*NC + Cn;
                    __half2 sh = *(const __half2*)(Ah  + idx);
                    __half2 sl = *(const __half2*)(Alo + idx);
                    float a0 = __half2float(sh.x) + __half2float(sl.x);
                    float a1 = __half2float(sh.y) + __half2float(sl.y);
                    float r0 = a0 + 0.1f*tanhf(v0);
                    float r1 = a1 + 0.1f*tanhf(v1);
                    __half h0 = __float2half_rn(r0);
                    __half h1 = __float2half_rn(r1);
                    __half2 hp; hp.x = h0; hp.y = h1;
                    *(__half2*)(ohi + idx) = hp;
                    __half2 lp;
                    lp.x = __float2half_rn(r0 - __half2float(h0));
                    lp.y = __float2half_rn(r1 - __half2float(h1));
                    *(__half2*)(olo + idx) = lp;
                } else {
                    int b = R >> 10, sp = R & 1023;
                    size_t basei = (size_t)(b*NC + Cn)*NS + sp;
                    // exact residual: hi+lo storage pair
                    size_t idx = (size_t)R*NC + Cn;
                    __half2 sh = *(const __half2*)(Ah  + idx);
                    __half2 sl = *(const __half2*)(Alo + idx);
                    (void)sh; (void)sl;
                    out[basei     ] = addsrc[basei     ] + v0;
                    out[basei + NS] = addsrc[basei + NS] + v1;
                }
            }
        }
    }
}

// ============================================================
// FA2 mma.sync fp16 1-term attention.
// ============================================================
#define APITCH 144
#define ATILE  (128*APITCH)          // 18432 bytes
#define ABUF   (2*ATILE)             // Kh | Vh
#define ATT_SMEM (2*ABUF)            // 73728

__global__ void __launch_bounds__(256, 1) attn_kernel() {
    extern __shared__ char smem[];
    uint32_t sb = smem_u32(smem);
    int tid = threadIdx.x, lane = tid & 31, w = tid >> 5;
    int qt = blockIdx.x, h = blockIdx.y, b = blockIdx.z;
    int g = lane >> 2, tig = lane & 3;
    size_t bh_off = (size_t)(b*NHD + h)*NS*HD;

    const __half* Kh = g_kh + bh_off;
    const __half* Vh = g_vh + bh_off;

    auto load_kv = [&](int kt, int bb) {
        size_t t0HD = (size_t)(kt << 7) * HD;
        uint32_t base = sb + bb*ABUF;
#pragma unroll
        for (int it = 0; it < 4; it++) {
            int chunk = tid + it*256;
            int r = chunk >> 3, c = chunk & 7;
            uint32_t so = r*APITCH + c*16;
            size_t goff = t0HD + (size_t)r*HD + c*8;
            cp16(base + so,         Kh + goff);
            cp16(base + ATILE + so, Vh + goff);
        }
        CP_COMMIT();
    };

    load_kv(0, 0);

    // ---- Q frags direct from gmem ----
    uint32_t qh[4][4];
    {
        const __half* Qh = g_qh + bh_off + (size_t)(qt<<7)*HD;
        int r0 = w*16 + g;
#pragma unroll
        for (int ks = 0; ks < 4; ks++) {
            int c0 = ks*16 + tig*2;
            qh[ks][0] = *(const uint32_t*)(Qh + (size_t)r0*HD + c0);
            qh[ks][1] = *(const uint32_t*)(Qh + (size_t)(r0+8)*HD + c0);
            qh[ks][2] = *(const uint32_t*)(Qh + (size_t)r0*HD + c0 + 8);
            qh[ks][3] = *(const uint32_t*)(Qh + (size_t)(r0+8)*HD + c0 + 8);
        }
    }

    float O[8][4] = {};
    float m0 = -1e30f, m1 = -1e30f, l0 = 0.f, l1 = 0.f;

    uint32_t kOff = (uint32_t)(((lane >> 4) & 1)*8 + (lane & 7))*APITCH
                  + ((lane >> 3) & 1)*16;
    uint32_t vOff = (uint32_t)ATILE
                  + (uint32_t)(((lane >> 3) & 1)*8 + (lane & 7))*APITCH
                  + ((lane >> 4) & 1)*16;

    int buf = 0;
    for (int kt = 0; kt < 8; kt++) {
        if (kt < 7) { load_kv(kt + 1, buf ^ 1); CP_WAIT1(); }
        else        { CP_WAIT0(); }
        __syncthreads();
        uint32_t base = sb + buf*ABUF;

        // ---- S = Q K^T ----
        float S[16][4];
#pragma unroll
        for (int i = 0; i < 16; i++) { S[i][0]=0.f; S[i][1]=0.f; S[i][2]=0.f; S[i][3]=0.f; }
#pragma unroll
        for (int ks = 0; ks < 4; ks++) {
#pragma unroll
            for (int nf = 0; nf < 8; nf++) {
                uint32_t kh4[4];
                uint32_t adr = base + kOff + nf*(16*APITCH) + ks*32;
                ldsm4(kh4[0], kh4[1], kh4[2], kh4[3], adr);
                mma16816(S[2*nf],   qh[ks], &kh4[0]);
                mma16816(S[2*nf+1], qh[ks], &kh4[2]);
            }
        }
#pragma unroll
        for (int i = 0; i < 16; i++) {
            S[i][0] *= QSCALE; S[i][1] *= QSCALE;
            S[i][2] *= QSCALE; S[i][3] *= QSCALE;
        }

        // ---- softmax (base-2) ----
        float mx0 = -1e30f, mx1 = -1e30f;
#pragma unroll
        for (int i = 0; i < 16; i++) {
            mx0 = fmaxf(mx0, fmaxf(S[i][0], S[i][1]));
            mx1 = fmaxf(mx1, fmaxf(S[i][2], S[i][3]));
        }
        mx0 = fmaxf(mx0, __shfl_xor_sync(0xffffffff, mx0, 1));
        mx0 = fmaxf(mx0, __shfl_xor_sync(0xffffffff, mx0, 2));
        mx1 = fmaxf(mx1, __shfl_xor_sync(0xffffffff, mx1, 1));
        mx1 = fmaxf(mx1, __shfl_xor_sync(0xffffffff, mx1, 2));
        float mn0 = fmaxf(m0, mx0), mn1 = fmaxf(m1, mx1);
        float al0 = exp2f(m0 - mn0), al1 = exp2f(m1 - mn1);
        m0 = mn0; m1 = mn1;
        float sum0 = 0.f, sum1 = 0.f;
#pragma unroll
        for (int i = 0; i < 16; i++) {
            S[i][0] = exp2f(S[i][0] - mn0);
            S[i][1] = exp2f(S[i][1] - mn0);
            S[i][2] = exp2f(S[i][2] - mn1);
            S[i][3] = exp2f(S[i][3] - mn1);
            sum0 += S[i][0] + S[i][1];
            sum1 += S[i][2] + S[i][3];
        }
        sum0 += __shfl_xor_sync(0xffffffff, sum0, 1);
        sum0 += __shfl_xor_sync(0xffffffff, sum0, 2);
        sum1 += __shfl_xor_sync(0xffffffff, sum1, 1);
        sum1 += __shfl_xor_sync(0xffffffff, sum1, 2);
        l0 = l0*al0 + sum0;
        l1 = l1*al1 + sum1;
#pragma unroll
        for (int of = 0; of < 8; of++) {
            O[of][0]*=al0; O[of][1]*=al0; O[of][2]*=al1; O[of][3]*=al1;
        }

        // ---- O += P V ----
#pragma unroll
        for (int t16 = 0; t16 < 8; t16++) {
            float* c0 = S[2*t16];
            float* c1 = S[2*t16+1];
            uint32_t pha[4];
            {
                __half2 t;
                t = __floats2half2_rn(c0[0], c0[1]); pha[0]=*(uint32_t*)&t;
                t = __floats2half2_rn(c0[2], c0[3]); pha[1]=*(uint32_t*)&t;
                t = __floats2half2_rn(c1[0], c1[1]); pha[2]=*(uint32_t*)&t;
                t = __floats2half2_rn(c1[2], c1[3]); pha[3]=*(uint32_t*)&t;
            }
#pragma unroll
            for (int db = 0; db < 4; db++) {
                uint32_t vh4[4];
                uint32_t adr = base + vOff + t16*(16*APITCH) + db*32;
                ldsm4t(vh4[0], vh4[1], vh4[2], vh4[3], adr);
                mma16816(O[2*db],   pha, &vh4[0]);
                mma16816(O[2*db+1], pha, &vh4[2]);
            }
        }
        __syncthreads();
        buf ^= 1;
    }

    // ---- epilogue: normalize, write hi/lo storage pair ----
    float inv0 = 1.f / l0, inv1 = 1.f / l1;
    int r0g = (qt<<7) + w*16 + g;
#pragma unroll
    for (int of = 0; of < 8; of++) {
        int d0 = of*8 + tig*2;
        float a0 = O[of][0]*inv0, a1 = O[of][1]*inv0;
        float a2 = O[of][2]*inv1, a3 = O[of][3]*inv1;
        size_t i0 = (size_t)(b*NS + r0g)*NC + h*HD + d0;
        size_t i1 = (size_t)(b*NS + r0g + 8)*NC + h*HD + d0;
        __half h0 = __float2half_rn(a0), h1 = __float2half_rn(a1);
        __half h2 = __float2half_rn(a2), h3 = __float2half_rn(a3);
        __half2 p;
        p.x=h0; p.y=h1; *(__half2*)(g_hf_hi + i0) = p;
        p.x=h2; p.y=h3; *(__half2*)(g_hf_hi + i1) = p;
        p.x=__float2half_rn(a0-__half2float(h0));
        p.y=__float2half_rn(a1-__half2float(h1));
        *(__half2*)(g_hf_lo + i0) = p;
        p.x=__float2half_rn(a2-__half2float(h2));
        p.y=__float2half_rn(a3-__half2float(h3));
        *(__half2*)(g_hf_lo + i1) = p;
    }
}

// ============================================================
// launch
// ============================================================
extern "C" void kernel_launch(void* const* d_in, const int* in_sizes, int n_in,
                              void* d_out, int out_size) {
    const float* x      = (const float*)d_in[0];
    const float* gns    = (const float*)d_in[1];
    const float* gnb    = (const float*)d_in[2];
    const float* qkv_w  = (const float*)d_in[3];
    const float* qkv_b  = (const float*)d_in[4];
    const float* proj_w = (const float*)d_in[5];
    const float* proj_b = (const float*)d_in[6];
    const float* inl_w  = (const float*)d_in[7];
    const float* inl_b  = (const float*)d_in[8];
    float* out = (float*)d_out;

    __half *hh, *wqh, *wih, *wph;
    __half *hfh, *hfl, *hf2h, *hf2l;
    cudaGetSymbolAddress((void**)&hh,   g_h_hi);
    cudaGetSymbolAddress((void**)&wqh,  g_wq_hi);
    cudaGetSymbolAddress((void**)&wih,  g_wi_hi);
    cudaGetSymbolAddress((void**)&wph,  g_wp_hi);
    cudaGetSymbolAddress((void**)&hfh,  g_hf_hi);
    cudaGetSymbolAddress((void**)&hfl,  g_hf_lo);
    cudaGetSymbolAddress((void**)&hf2h, g_hf2_hi);
    cudaGetSymbolAddress((void**)&hf2l, g_hf2_lo);

    cudaFuncSetAttribute((const void*)attn_kernel,
                         cudaFuncAttributeMaxDynamicSharedMemorySize, ATT_SMEM);
    cudaFuncSetAttribute((const void*)mm_gemm<0>,
                         cudaFuncAttributeMaxDynamicSharedMemorySize, GEMM_SMEM);
    cudaFuncSetAttribute((const void*)mm_gemm<1>,
                         cudaFuncAttributeMaxDynamicSharedMemorySize, GEMM_SMEM);
    cudaFuncSetAttribute((const void*)mm_gemm<2>,
                         cudaFuncAttributeMaxDynamicSharedMemorySize, GEMM_SMEM);

    cvt_kernel<<<(3*NC*NC + 255)/256, 256>>>(qkv_w,  wqh, 3*NC*NC);
    cvt_kernel<<<(NC*NC   + 255)/256, 256>>>(inl_w,  wih, NC*NC);
    cvt_kernel<<<(NC*NC   + 255)/256, 256>>>(proj_w, wph, NC*NC);
    gn_stats1<<<512, 256>>>(x);
    gn_stats2<<<1, 64>>>();
    gn_apply<<<dim3(16, 8, 8), 256>>>(x, gns, gnb);

    mm_gemm<0><<<dim3(12, 64), 256, GEMM_SMEM>>>(hh, nullptr, wqh, qkv_b,
                                                 nullptr, nullptr, nullptr, nullptr);
    attn_kernel<<<dim3(8, 8, 8), 256, ATT_SMEM>>>();
    mm_gemm<1><<<dim3(4, 64), 256, GEMM_SMEM>>>(hfh, hfl, wih, inl_b,
                                                nullptr, nullptr, hf2h, hf2l);
    mm_gemm<1><<<dim3(4, 64), 256, GEMM_SMEM>>>(hf2h, hf2l, wih, inl_b,
                                                nullptr, nullptr, hfh, hfl);
    mm_gemm<1><<<dim3(4, 64), 256, GEMM_SMEM>>>(hfh, hfl, wih, inl_b,
                                                nullptr, nullptr, hf2h, hf2l);
    mm_gemm<2><<<dim3(4, 64), 256, GEMM_SMEM>>>(hf2h, hf2l, wph, proj_b,
                                                x, out, nullptr, nullptr);
}